// round 1
// baseline (speedup 1.0000x reference)
#include <cuda_runtime.h>
#include <math.h>

#define N_TOK 8192
#define C_DIM 768
#define E_NUM 8
#define H_DIM 3072

// ---------------- device scratch (no runtime allocation) ----------------
__device__ int   g_counts[E_NUM];
__device__ int   g_tok   [E_NUM * N_TOK];   // token index per list entry
__device__ int   g_hrow  [E_NUM * N_TOK];   // selection row = token*2 + k
__device__ float g_prob  [E_NUM * N_TOK];   // renormalized gate prob
__device__ float g_h     [(size_t)2 * N_TOK * H_DIM];  // 201 MB: GELU(x@w1+b1) rows
__device__ float g_outbuf[(size_t)2 * N_TOK * C_DIM];  // 50 MB: per-selection outputs

// ---------------- kernel 0: zero counters ----------------
__global__ void zero_counts_kernel() {
    if (threadIdx.x < E_NUM) g_counts[threadIdx.x] = 0;
}

// ---------------- kernel 1: gate + top-2 routing ----------------
// one warp per token
__global__ void gate_kernel(const float* __restrict__ x,
                            const float* __restrict__ gw,
                            const float* __restrict__ gb) {
    int warp = (blockIdx.x * blockDim.x + threadIdx.x) >> 5;
    int lane = threadIdx.x & 31;
    if (warp >= N_TOK) return;
    int token = warp;

    float acc[8];
#pragma unroll
    for (int e = 0; e < 8; e++) acc[e] = 0.f;

    const float* xr = x + (size_t)token * C_DIM;
#pragma unroll 4
    for (int c = lane; c < C_DIM; c += 32) {
        float xv = xr[c];
        const float4* g4 = reinterpret_cast<const float4*>(gw + (size_t)c * E_NUM);
        float4 g0 = g4[0];
        float4 g1 = g4[1];
        acc[0] += xv * g0.x; acc[1] += xv * g0.y;
        acc[2] += xv * g0.z; acc[3] += xv * g0.w;
        acc[4] += xv * g1.x; acc[5] += xv * g1.y;
        acc[6] += xv * g1.z; acc[7] += xv * g1.w;
    }
#pragma unroll
    for (int e = 0; e < 8; e++) {
#pragma unroll
        for (int off = 16; off > 0; off >>= 1)
            acc[e] += __shfl_xor_sync(0xffffffffu, acc[e], off);
    }

    if (lane == 0) {
        float best_v = -1e30f, sec_v = -1e30f;
        int best_e = 0, sec_e = 0;
#pragma unroll
        for (int e = 0; e < 8; e++) {
            float v = acc[e] + gb[e];
            if (v > best_v) { sec_v = best_v; sec_e = best_e; best_v = v; best_e = e; }
            else if (v > sec_v) { sec_v = v; sec_e = e; }
        }
        // pairwise softmax == renormalized top-2 of full softmax
        float z  = expf(sec_v - best_v);
        float p0 = 1.0f / (1.0f + z);
        float p1 = 1.0f - p0;

        int s0 = atomicAdd(&g_counts[best_e], 1);
        g_tok [best_e * N_TOK + s0] = token;
        g_hrow[best_e * N_TOK + s0] = token * 2;
        g_prob[best_e * N_TOK + s0] = p0;

        int s1 = atomicAdd(&g_counts[sec_e], 1);
        g_tok [sec_e * N_TOK + s1] = token;
        g_hrow[sec_e * N_TOK + s1] = token * 2 + 1;
        g_prob[sec_e * N_TOK + s1] = p1;
    }
}

// ---------------- kernel 2: grouped GEMM1 + bias + exact GELU ----------------
// h[sel] = gelu(x[tok] @ w1[e] + b1[e]);  tile 128x128, K-step 8, 256 thr, 8x8 micro
__global__ __launch_bounds__(256, 2)
void gemm1_kernel(const float* __restrict__ x,
                  const float* __restrict__ w1,
                  const float* __restrict__ b1) {
    int e  = blockIdx.z;
    int ne = g_counts[e];
    int m0 = blockIdx.y * 128;
    if (m0 >= ne) return;
    int n0 = blockIdx.x * 128;

    __shared__ int   s_tok [128];
    __shared__ int   s_hrow[128];
    __shared__ float As[8][128];
    __shared__ float Bs[8][128];

    int tid = threadIdx.x;
    if (tid < 128) {
        int idx = m0 + tid;
        if (idx < ne) {
            s_tok [tid] = g_tok [e * N_TOK + idx];
            s_hrow[tid] = g_hrow[e * N_TOK + idx];
        } else {
            s_tok [tid] = -1;
            s_hrow[tid] = -1;
        }
    }
    __syncthreads();

    const float* Bp = w1 + (size_t)e * C_DIM * H_DIM;

    float acc[8][8];
#pragma unroll
    for (int i = 0; i < 8; i++)
#pragma unroll
        for (int j = 0; j < 8; j++) acc[i][j] = 0.f;

    int ar = tid >> 1,  ak = (tid & 1) * 4;   // A loader: row, k-quad
    int bk = tid >> 5,  bn = (tid & 31) * 4;  // B loader: k, n-quad
    int tx = tid & 15,  ty = tid >> 4;        // microtile coords
    int atok = s_tok[ar];

    for (int k0 = 0; k0 < C_DIM; k0 += 8) {
        float4 av = make_float4(0.f, 0.f, 0.f, 0.f);
        if (atok >= 0)
            av = *reinterpret_cast<const float4*>(x + (size_t)atok * C_DIM + k0 + ak);
        float4 bv = *reinterpret_cast<const float4*>(Bp + (size_t)(k0 + bk) * H_DIM + n0 + bn);

        As[ak + 0][ar] = av.x; As[ak + 1][ar] = av.y;
        As[ak + 2][ar] = av.z; As[ak + 3][ar] = av.w;
        *reinterpret_cast<float4*>(&Bs[bk][bn]) = bv;
        __syncthreads();

#pragma unroll
        for (int kk = 0; kk < 8; kk++) {
            float a[8], b[8];
#pragma unroll
            for (int i = 0; i < 8; i++) a[i] = As[kk][ty * 8 + i];
#pragma unroll
            for (int j = 0; j < 8; j++) b[j] = Bs[kk][tx * 8 + j];
#pragma unroll
            for (int i = 0; i < 8; i++)
#pragma unroll
                for (int j = 0; j < 8; j++) acc[i][j] += a[i] * b[j];
        }
        __syncthreads();
    }

    const float* b1p = b1 + (size_t)e * H_DIM + n0 + tx * 8;
#pragma unroll
    for (int i = 0; i < 8; i++) {
        int hr = s_hrow[ty * 8 + i];
        if (hr < 0) continue;
        float* hp = g_h + (size_t)hr * H_DIM + n0 + tx * 8;
#pragma unroll
        for (int j = 0; j < 8; j++) {
            float v = acc[i][j] + b1p[j];
            v = 0.5f * v * (1.0f + erff(v * 0.70710678118654752f));
            hp[j] = v;
        }
    }
}

// ---------------- kernel 3: grouped GEMM2 + bias + prob scale ----------------
// outbuf[sel] = (h[sel] @ w2[e] + b2[e]) * prob
__global__ __launch_bounds__(256, 2)
void gemm2_kernel(const float* __restrict__ w2,
                  const float* __restrict__ b2) {
    int e  = blockIdx.z;
    int ne = g_counts[e];
    int m0 = blockIdx.y * 128;
    if (m0 >= ne) return;
    int n0 = blockIdx.x * 128;

    __shared__ int   s_hrow[128];
    __shared__ float s_prob[128];
    __shared__ float As[8][128];
    __shared__ float Bs[8][128];

    int tid = threadIdx.x;
    if (tid < 128) {
        int idx = m0 + tid;
        if (idx < ne) {
            s_hrow[tid] = g_hrow[e * N_TOK + idx];
            s_prob[tid] = g_prob[e * N_TOK + idx];
        } else {
            s_hrow[tid] = -1;
            s_prob[tid] = 0.f;
        }
    }
    __syncthreads();

    const float* Bp = w2 + (size_t)e * H_DIM * C_DIM;

    float acc[8][8];
#pragma unroll
    for (int i = 0; i < 8; i++)
#pragma unroll
        for (int j = 0; j < 8; j++) acc[i][j] = 0.f;

    int ar = tid >> 1,  ak = (tid & 1) * 4;
    int bk = tid >> 5,  bn = (tid & 31) * 4;
    int tx = tid & 15,  ty = tid >> 4;
    int ahr = s_hrow[ar];

    for (int k0 = 0; k0 < H_DIM; k0 += 8) {
        float4 av = make_float4(0.f, 0.f, 0.f, 0.f);
        if (ahr >= 0)
            av = *reinterpret_cast<const float4*>(g_h + (size_t)ahr * H_DIM + k0 + ak);
        float4 bv = *reinterpret_cast<const float4*>(Bp + (size_t)(k0 + bk) * C_DIM + n0 + bn);

        As[ak + 0][ar] = av.x; As[ak + 1][ar] = av.y;
        As[ak + 2][ar] = av.z; As[ak + 3][ar] = av.w;
        *reinterpret_cast<float4*>(&Bs[bk][bn]) = bv;
        __syncthreads();

#pragma unroll
        for (int kk = 0; kk < 8; kk++) {
            float a[8], b[8];
#pragma unroll
            for (int i = 0; i < 8; i++) a[i] = As[kk][ty * 8 + i];
#pragma unroll
            for (int j = 0; j < 8; j++) b[j] = Bs[kk][tx * 8 + j];
#pragma unroll
            for (int i = 0; i < 8; i++)
#pragma unroll
                for (int j = 0; j < 8; j++) acc[i][j] += a[i] * b[j];
        }
        __syncthreads();
    }

    const float* b2p = b2 + (size_t)e * C_DIM + n0 + tx * 8;
#pragma unroll
    for (int i = 0; i < 8; i++) {
        int hr = s_hrow[ty * 8 + i];
        if (hr < 0) continue;
        float p = s_prob[ty * 8 + i];
        float* op = g_outbuf + (size_t)hr * C_DIM + n0 + tx * 8;
#pragma unroll
        for (int j = 0; j < 8; j++)
            op[j] = (acc[i][j] + b2p[j]) * p;
    }
}

// ---------------- kernel 4: combine top-2 contributions ----------------
__global__ void combine_kernel(float* __restrict__ out) {
    int i = blockIdx.x * blockDim.x + threadIdx.x;
    if (i >= N_TOK * C_DIM) return;
    int t = i / C_DIM;
    int c = i - t * C_DIM;
    out[i] = g_outbuf[(size_t)(2 * t) * C_DIM + c] +
             g_outbuf[(size_t)(2 * t + 1) * C_DIM + c];
}

// ---------------- launcher ----------------
extern "C" void kernel_launch(void* const* d_in, const int* in_sizes, int n_in,
                              void* d_out, int out_size) {
    const float* x      = (const float*)d_in[0];
    const float* gate_w = (const float*)d_in[1];
    const float* gate_b = (const float*)d_in[2];
    const float* w1     = (const float*)d_in[3];
    const float* b1     = (const float*)d_in[4];
    const float* w2     = (const float*)d_in[5];
    const float* b2     = (const float*)d_in[6];
    float* out = (float*)d_out;

    zero_counts_kernel<<<1, 32>>>();
    gate_kernel<<<N_TOK / 8, 256>>>(x, gate_w, gate_b);

    dim3 g1(H_DIM / 128, N_TOK / 128, E_NUM);   // (24, 64, 8)
    gemm1_kernel<<<g1, 256>>>(x, w1, b1);

    dim3 g2(C_DIM / 128, N_TOK / 128, E_NUM);   // (6, 64, 8)
    gemm2_kernel<<<g2, 256>>>(w2, b2);

    combine_kernel<<<(N_TOK * C_DIM + 255) / 256, 256>>>(out);
}

// round 5
// speedup vs baseline: 1.7880x; 1.7880x over previous
#include <cuda_runtime.h>
#include <cuda_bf16.h>
#include <math.h>
#include <stdint.h>

#define N_TOK 8192
#define C_DIM 768
#define E_NUM 8
#define H_DIM 3072
#define NSEL  (2*N_TOK)

// ---------------- device scratch (no runtime allocation) ----------------
__device__ int   g_counts[E_NUM];
__device__ int   g_tok [E_NUM*N_TOK];
__device__ int   g_hrow[E_NUM*N_TOK];
__device__ float g_prob[E_NUM*N_TOK];
__device__ __nv_bfloat16 g_xhi[N_TOK*C_DIM];
__device__ __nv_bfloat16 g_xlo[N_TOK*C_DIM];
__device__ __nv_bfloat16 g_w1hi[E_NUM*H_DIM*C_DIM];   // [e][h][c]  (K-major)
__device__ __nv_bfloat16 g_w1lo[E_NUM*H_DIM*C_DIM];
__device__ __nv_bfloat16 g_w2hi[E_NUM*C_DIM*H_DIM];   // [e][c][h]  (K-major)
__device__ __nv_bfloat16 g_w2lo[E_NUM*C_DIM*H_DIM];
__device__ __nv_bfloat16 g_hhi[(size_t)NSEL*H_DIM];
__device__ __nv_bfloat16 g_hlo[(size_t)NSEL*H_DIM];
__device__ float g_outbuf[(size_t)NSEL*C_DIM];

// ---------------- mma.sync m16n8k16 bf16 (sm_80 baseline) ----------------
__device__ __forceinline__ void mma_bf16(float* d, const uint32_t* a, const uint32_t* b) {
    asm volatile(
        "mma.sync.aligned.m16n8k16.row.col.f32.bf16.bf16.f32 "
        "{%0,%1,%2,%3}, {%4,%5,%6,%7}, {%8,%9}, {%0,%1,%2,%3};"
        : "+f"(d[0]), "+f"(d[1]), "+f"(d[2]), "+f"(d[3])
        : "r"(a[0]), "r"(a[1]), "r"(a[2]), "r"(a[3]), "r"(b[0]), "r"(b[1]));
}

// SMEM tile geometry: rows padded to 40 bf16 = 80B (16B aligned)
#define ROW_B   80
#define ARR_B   (128 * ROW_B)          // 10240 B per operand array
#define OFF_AHI 0
#define OFF_ALO (1 * ARR_B)
#define OFF_BHI (2 * ARR_B)
#define OFF_BLO (3 * ARR_B)
#define STAGE_B (4 * ARR_B)            // 40960 B (single stage)
#define TILE0   2048                   // meta region before tiles
#define SMEM_SZ (TILE0 + STAGE_B)      // 43008 B

// ---------------- kernel 0: zero counters ----------------
__global__ void zero_counts_kernel() {
    if (threadIdx.x < E_NUM) g_counts[threadIdx.x] = 0;
}

// ---------------- kernel 1: gate + top-2 routing (one warp/token) ----------------
__global__ void gate_kernel(const float* __restrict__ x,
                            const float* __restrict__ gw,
                            const float* __restrict__ gb) {
    int warp = (blockIdx.x * blockDim.x + threadIdx.x) >> 5;
    int lane = threadIdx.x & 31;
    if (warp >= N_TOK) return;
    int token = warp;

    float acc[8];
#pragma unroll
    for (int e = 0; e < 8; e++) acc[e] = 0.f;

    const float* xr = x + (size_t)token * C_DIM;
#pragma unroll 4
    for (int c = lane; c < C_DIM; c += 32) {
        float xv = xr[c];
        const float4* g4 = reinterpret_cast<const float4*>(gw + (size_t)c * E_NUM);
        float4 g0 = g4[0];
        float4 g1 = g4[1];
        acc[0] += xv * g0.x; acc[1] += xv * g0.y;
        acc[2] += xv * g0.z; acc[3] += xv * g0.w;
        acc[4] += xv * g1.x; acc[5] += xv * g1.y;
        acc[6] += xv * g1.z; acc[7] += xv * g1.w;
    }
#pragma unroll
    for (int e = 0; e < 8; e++) {
#pragma unroll
        for (int off = 16; off > 0; off >>= 1)
            acc[e] += __shfl_xor_sync(0xffffffffu, acc[e], off);
    }

    if (lane == 0) {
        float best_v = -1e30f, sec_v = -1e30f;
        int best_e = 0, sec_e = 0;
#pragma unroll
        for (int e = 0; e < 8; e++) {
            float v = acc[e] + gb[e];
            if (v > best_v) { sec_v = best_v; sec_e = best_e; best_v = v; best_e = e; }
            else if (v > sec_v) { sec_v = v; sec_e = e; }
        }
        float z  = expf(sec_v - best_v);
        float p0 = 1.0f / (1.0f + z);
        float p1 = 1.0f - p0;

        int s0 = atomicAdd(&g_counts[best_e], 1);
        g_tok [best_e * N_TOK + s0] = token;
        g_hrow[best_e * N_TOK + s0] = token * 2;
        g_prob[best_e * N_TOK + s0] = p0;

        int s1 = atomicAdd(&g_counts[sec_e], 1);
        g_tok [sec_e * N_TOK + s1] = token;
        g_hrow[sec_e * N_TOK + s1] = token * 2 + 1;
        g_prob[sec_e * N_TOK + s1] = p1;
    }
}

// ---------------- kernel 2: split x -> bf16 hi/lo ----------------
__global__ void convert_x_kernel(const float* __restrict__ x) {
    int i = blockIdx.x * blockDim.x + threadIdx.x;   // over N_TOK*C_DIM/4
    float4 v = reinterpret_cast<const float4*>(x)[i];
    float f[4] = {v.x, v.y, v.z, v.w};
    __nv_bfloat16 hi[4], lo[4];
#pragma unroll
    for (int j = 0; j < 4; j++) {
        hi[j] = __float2bfloat16_rn(f[j]);
        lo[j] = __float2bfloat16_rn(f[j] - __bfloat162float(hi[j]));
    }
    __nv_bfloat162* ph = reinterpret_cast<__nv_bfloat162*>(g_xhi);
    __nv_bfloat162* pl = reinterpret_cast<__nv_bfloat162*>(g_xlo);
    ph[i * 2 + 0] = __nv_bfloat162(hi[0], hi[1]);
    ph[i * 2 + 1] = __nv_bfloat162(hi[2], hi[3]);
    pl[i * 2 + 0] = __nv_bfloat162(lo[0], lo[1]);
    pl[i * 2 + 1] = __nv_bfloat162(lo[2], lo[3]);
}

// ---------------- kernel 3: transpose + split weights ----------------
// in: [E][R][S] fp32  ->  out: [E][S][R] bf16 hi/lo
// FIX (round 5): destination __device__ symbols selected in DEVICE code.
// Passing g_w1hi/... as host-side kernel args silently bound the host shadow
// symbol address (ATS-writable on GB300) -> device symbols stayed zero.
__global__ void transpose_conv_kernel(const float* __restrict__ in,
                                      int which, int R, int S) {
    __nv_bfloat16* __restrict__ ohi = which ? g_w2hi : g_w1hi;
    __nv_bfloat16* __restrict__ olo = which ? g_w2lo : g_w1lo;
    __shared__ float t[32][33];
    int e = blockIdx.z;
    int r0 = blockIdx.y * 32, s0 = blockIdx.x * 32;
    const float* ip = in + (size_t)e * R * S;
    for (int j = threadIdx.y; j < 32; j += 8)
        t[j][threadIdx.x] = ip[(size_t)(r0 + j) * S + s0 + threadIdx.x];
    __syncthreads();
    size_t ob = (size_t)e * R * S;
    for (int j = threadIdx.y; j < 32; j += 8) {
        float v = t[threadIdx.x][j];                  // in[r0+tx][s0+j]
        __nv_bfloat16 hi = __float2bfloat16_rn(v);
        __nv_bfloat16 lo = __float2bfloat16_rn(v - __bfloat162float(hi));
        size_t o = ob + (size_t)(s0 + j) * R + r0 + threadIdx.x;
        ohi[o] = hi;
        olo[o] = lo;
    }
}

// ---------------- grouped GEMM: mma.sync bf16, 3-term split ----------------
// D[128 sel rows, 128 cols] = Ahi*Bhi^T + Ahi*Blo^T + Alo*Bhi^T  (fp32 acc)
// Register-prefetch pipeline, plain LDG/STS.
template<int KDIM, bool IS_G1>
__global__ __launch_bounds__(256, 1)
void moe_gemm_kernel(const float* __restrict__ bias) {
    constexpr int NDIM = IS_G1 ? H_DIM : C_DIM;
    constexpr int NCH  = KDIM / 32;

    int e  = blockIdx.z;
    int ne = g_counts[e];
    int m0 = blockIdx.y * 128;
    if (m0 >= ne) return;
    int n0 = blockIdx.x * 128;

    extern __shared__ char smem[];
    int*   s_hrow = (int*)(smem);            // 512 B
    float* s_prob = (float*)(smem + 512);    // 512 B
    int*   s_gidx = (int*)(smem + 1024);     // 512 B

    int tid = threadIdx.x, wid = tid >> 5, lane = tid & 31;

    if (tid < 128) {
        int idx = m0 + tid;
        int g = -1, hr = -1; float p = 0.f;
        if (idx < ne) {
            g  = IS_G1 ? g_tok[e * N_TOK + idx] : g_hrow[e * N_TOK + idx];
            hr = g_hrow[e * N_TOK + idx];
            p  = g_prob[e * N_TOK + idx];
        }
        s_gidx[tid] = g;
        s_hrow[tid] = hr;
        s_prob[tid] = p;
    }
    __syncthreads();

    const __nv_bfloat16* __restrict__ Ahi = IS_G1 ? g_xhi : g_hhi;
    const __nv_bfloat16* __restrict__ Alo = IS_G1 ? g_xlo : g_hlo;
    const __nv_bfloat16* __restrict__ Bhi = IS_G1 ? g_w1hi : g_w2hi;
    const __nv_bfloat16* __restrict__ Blo = IS_G1 ? g_w1lo : g_w2lo;

    // loader mapping: thread t -> tile row t>>1, k-half t&1 (16 elems = 32 B)
    int lrow = tid >> 1, lhalf = tid & 1;
    int arow = s_gidx[lrow];
    size_t abase = (size_t)(arow < 0 ? 0 : arow) * KDIM + lhalf * 16;
    size_t bbase = ((size_t)e * NDIM + n0 + lrow) * KDIM + lhalf * 16;
    uint32_t ldst = lrow * ROW_B + lhalf * 32;   // byte offset within operand array

    char* tile = smem + TILE0;

    uint4 rAh0, rAh1, rAl0, rAl1, rBh0, rBh1, rBl0, rBl1;
    const uint4 z4 = make_uint4(0, 0, 0, 0);

    // load chunk 0
    {
        const uint4* pAh = (const uint4*)(Ahi + abase);
        const uint4* pAl = (const uint4*)(Alo + abase);
        const uint4* pBh = (const uint4*)(Bhi + bbase);
        const uint4* pBl = (const uint4*)(Blo + bbase);
        rAh0 = (arow >= 0) ? pAh[0] : z4;  rAh1 = (arow >= 0) ? pAh[1] : z4;
        rAl0 = (arow >= 0) ? pAl[0] : z4;  rAl1 = (arow >= 0) ? pAl[1] : z4;
        rBh0 = pBh[0];  rBh1 = pBh[1];
        rBl0 = pBl[0];  rBl1 = pBl[1];
    }

    // compute-thread mapping
    int wm = wid >> 2, wn = wid & 3;     // warp tile: rows wm*64.., cols wn*32..
    int lr = lane >> 2, lc2 = (lane & 3) * 2;

    float acc[4][4][4];
#pragma unroll
    for (int mt = 0; mt < 4; mt++)
#pragma unroll
        for (int nt = 0; nt < 4; nt++)
#pragma unroll
            for (int q = 0; q < 4; q++) acc[mt][nt][q] = 0.f;

    for (int c = 0; c < NCH; c++) {
        __syncthreads();   // previous compute done -> smem reusable
        *(uint4*)(tile + OFF_AHI + ldst)      = rAh0;
        *(uint4*)(tile + OFF_AHI + ldst + 16) = rAh1;
        *(uint4*)(tile + OFF_ALO + ldst)      = rAl0;
        *(uint4*)(tile + OFF_ALO + ldst + 16) = rAl1;
        *(uint4*)(tile + OFF_BHI + ldst)      = rBh0;
        *(uint4*)(tile + OFF_BHI + ldst + 16) = rBh1;
        *(uint4*)(tile + OFF_BLO + ldst)      = rBl0;
        *(uint4*)(tile + OFF_BLO + ldst + 16) = rBl1;
        __syncthreads();

        if (c + 1 < NCH) {               // prefetch next chunk (overlaps compute)
            size_t ka = abase + (size_t)(c + 1) * 32;
            size_t kb = bbase + (size_t)(c + 1) * 32;
            const uint4* pAh = (const uint4*)(Ahi + ka);
            const uint4* pAl = (const uint4*)(Alo + ka);
            const uint4* pBh = (const uint4*)(Bhi + kb);
            const uint4* pBl = (const uint4*)(Blo + kb);
            rAh0 = (arow >= 0) ? pAh[0] : z4;  rAh1 = (arow >= 0) ? pAh[1] : z4;
            rAl0 = (arow >= 0) ? pAl[0] : z4;  rAl1 = (arow >= 0) ? pAl[1] : z4;
            rBh0 = pBh[0];  rBh1 = pBh[1];
            rBl0 = pBl[0];  rBl1 = pBl[1];
        }

#pragma unroll
        for (int ks = 0; ks < 2; ks++) {
            int kb2 = (ks * 16 + lc2) * 2;   // byte offset of k element pair

            uint32_t ah[4][4];
#pragma unroll
            for (int mt = 0; mt < 4; mt++) {
                const char* ap = tile + OFF_AHI + (wm * 64 + mt * 16 + lr) * ROW_B;
                ah[mt][0] = *(const uint32_t*)(ap + kb2);
                ah[mt][1] = *(const uint32_t*)(ap + 8 * ROW_B + kb2);
                ah[mt][2] = *(const uint32_t*)(ap + kb2 + 16);
                ah[mt][3] = *(const uint32_t*)(ap + 8 * ROW_B + kb2 + 16);
            }
            uint32_t bh[4][2];
#pragma unroll
            for (int nt = 0; nt < 4; nt++) {
                const char* bp = tile + OFF_BHI + (wn * 32 + nt * 8 + lr) * ROW_B;
                bh[nt][0] = *(const uint32_t*)(bp + kb2);
                bh[nt][1] = *(const uint32_t*)(bp + kb2 + 16);
            }
#pragma unroll
            for (int mt = 0; mt < 4; mt++)
#pragma unroll
                for (int nt = 0; nt < 4; nt++)
                    mma_bf16(acc[mt][nt], ah[mt], bh[nt]);

            uint32_t bl[4][2];
#pragma unroll
            for (int nt = 0; nt < 4; nt++) {
                const char* bp = tile + OFF_BLO + (wn * 32 + nt * 8 + lr) * ROW_B;
                bl[nt][0] = *(const uint32_t*)(bp + kb2);
                bl[nt][1] = *(const uint32_t*)(bp + kb2 + 16);
            }
#pragma unroll
            for (int mt = 0; mt < 4; mt++)
#pragma unroll
                for (int nt = 0; nt < 4; nt++)
                    mma_bf16(acc[mt][nt], ah[mt], bl[nt]);

            uint32_t al[4][4];
#pragma unroll
            for (int mt = 0; mt < 4; mt++) {
                const char* ap = tile + OFF_ALO + (wm * 64 + mt * 16 + lr) * ROW_B;
                al[mt][0] = *(const uint32_t*)(ap + kb2);
                al[mt][1] = *(const uint32_t*)(ap + 8 * ROW_B + kb2);
                al[mt][2] = *(const uint32_t*)(ap + kb2 + 16);
                al[mt][3] = *(const uint32_t*)(ap + 8 * ROW_B + kb2 + 16);
            }
#pragma unroll
            for (int mt = 0; mt < 4; mt++)
#pragma unroll
                for (int nt = 0; nt < 4; nt++)
                    mma_bf16(acc[mt][nt], al[mt], bh[nt]);
        }
    }

    // ---- epilogue ----
#pragma unroll
    for (int nt = 0; nt < 4; nt++) {
        int col = n0 + wn * 32 + nt * 8 + lc2;
        float bb0 = bias[(size_t)e * NDIM + col];
        float bb1 = bias[(size_t)e * NDIM + col + 1];
#pragma unroll
        for (int mt = 0; mt < 4; mt++) {
            int r0 = wm * 64 + mt * 16 + lr;
#pragma unroll
            for (int rh = 0; rh < 2; rh++) {
                int rr = r0 + rh * 8;
                int hr = s_hrow[rr];
                if (hr < 0) continue;
                float v0 = acc[mt][nt][rh * 2 + 0] + bb0;
                float v1 = acc[mt][nt][rh * 2 + 1] + bb1;
                if (IS_G1) {
                    v0 = 0.5f * v0 * (1.0f + erff(v0 * 0.70710678118654752f));
                    v1 = 0.5f * v1 * (1.0f + erff(v1 * 0.70710678118654752f));
                    __nv_bfloat16 h0 = __float2bfloat16_rn(v0);
                    __nv_bfloat16 h1 = __float2bfloat16_rn(v1);
                    __nv_bfloat16 l0 = __float2bfloat16_rn(v0 - __bfloat162float(h0));
                    __nv_bfloat16 l1 = __float2bfloat16_rn(v1 - __bfloat162float(h1));
                    size_t ob = (size_t)hr * H_DIM + col;
                    *(__nv_bfloat162*)(g_hhi + ob) = __nv_bfloat162(h0, h1);
                    *(__nv_bfloat162*)(g_hlo + ob) = __nv_bfloat162(l0, l1);
                } else {
                    float p = s_prob[rr];
                    size_t ob = (size_t)hr * C_DIM + col;
                    *(float2*)(g_outbuf + ob) = make_float2(v0 * p, v1 * p);
                }
            }
        }
    }
}

// ---------------- kernel: combine top-2 contributions ----------------
__global__ void combine_kernel(float* __restrict__ out) {
    int i = blockIdx.x * blockDim.x + threadIdx.x;
    if (i >= N_TOK * C_DIM) return;
    int t = i / C_DIM;
    int c = i - t * C_DIM;
    out[i] = g_outbuf[(size_t)(2 * t) * C_DIM + c] +
             g_outbuf[(size_t)(2 * t + 1) * C_DIM + c];
}

// ---------------- launcher ----------------
extern "C" void kernel_launch(void* const* d_in, const int* in_sizes, int n_in,
                              void* d_out, int out_size) {
    const float* x      = (const float*)d_in[0];
    const float* gate_w = (const float*)d_in[1];
    const float* gate_b = (const float*)d_in[2];
    const float* w1     = (const float*)d_in[3];
    const float* b1     = (const float*)d_in[4];
    const float* w2     = (const float*)d_in[5];
    const float* b2     = (const float*)d_in[6];
    float* out = (float*)d_out;

    zero_counts_kernel<<<1, 32>>>();
    gate_kernel<<<N_TOK / 8, 256>>>(x, gate_w, gate_b);
    convert_x_kernel<<<(N_TOK * C_DIM / 4) / 256, 256>>>(x);

    dim3 t1(H_DIM / 32, C_DIM / 32, E_NUM);   // (96, 24, 8)
    transpose_conv_kernel<<<t1, dim3(32, 8)>>>(w1, 0, C_DIM, H_DIM);
    dim3 t2(C_DIM / 32, H_DIM / 32, E_NUM);   // (24, 96, 8)
    transpose_conv_kernel<<<t2, dim3(32, 8)>>>(w2, 1, H_DIM, C_DIM);

    dim3 g1(H_DIM / 128, 64, E_NUM);          // (24, 64, 8)
    moe_gemm_kernel<C_DIM, true><<<g1, 256, SMEM_SZ>>>(b1);

    dim3 g2(C_DIM / 128, 64, E_NUM);          // (6, 64, 8)
    moe_gemm_kernel<H_DIM, false><<<g2, 256, SMEM_SZ>>>(b2);

    combine_kernel<<<(N_TOK * C_DIM + 255) / 256, 256>>>(out);
}

// round 6
// speedup vs baseline: 2.0232x; 1.1316x over previous
#include <cuda_runtime.h>
#include <cuda_bf16.h>
#include <math.h>
#include <stdint.h>

#define N_TOK 8192
#define C_DIM 768
#define E_NUM 8
#define H_DIM 3072
#define NSEL  (2*N_TOK)

// ---------------- device scratch (no runtime allocation) ----------------
__device__ int   g_counts[E_NUM];
__device__ int   g_tok [E_NUM*N_TOK];
__device__ int   g_hrow[E_NUM*N_TOK];
__device__ float g_prob[E_NUM*N_TOK];
__device__ __nv_bfloat16 g_xhi[N_TOK*C_DIM];
__device__ __nv_bfloat16 g_xlo[N_TOK*C_DIM];
__device__ __nv_bfloat16 g_w1hi[E_NUM*H_DIM*C_DIM];   // [e][h][c]  (K-major)
__device__ __nv_bfloat16 g_w1lo[E_NUM*H_DIM*C_DIM];
__device__ __nv_bfloat16 g_w2hi[E_NUM*C_DIM*H_DIM];   // [e][c][h]  (K-major)
__device__ __nv_bfloat16 g_w2lo[E_NUM*C_DIM*H_DIM];
__device__ __nv_bfloat16 g_hhi[(size_t)NSEL*H_DIM];
__device__ __nv_bfloat16 g_hlo[(size_t)NSEL*H_DIM];
__device__ float g_outbuf[(size_t)NSEL*C_DIM];

// ---------------- low-level helpers (sm_80-era baseline) ----------------
__device__ __forceinline__ void cpa16(uint32_t dst, const void* src, uint32_t srcsz) {
    asm volatile("cp.async.cg.shared.global [%0], [%1], 16, %2;"
                 :: "r"(dst), "l"(src), "r"(srcsz) : "memory");
}
__device__ __forceinline__ void cpa_commit() {
    asm volatile("cp.async.commit_group;" ::: "memory");
}
template<int N>
__device__ __forceinline__ void cpa_wait() {
    asm volatile("cp.async.wait_group %0;" :: "n"(N) : "memory");
}
__device__ __forceinline__ void mma_bf16(float* d, const uint32_t* a, const uint32_t* b) {
    asm volatile(
        "mma.sync.aligned.m16n8k16.row.col.f32.bf16.bf16.f32 "
        "{%0,%1,%2,%3}, {%4,%5,%6,%7}, {%8,%9}, {%0,%1,%2,%3};"
        : "+f"(d[0]), "+f"(d[1]), "+f"(d[2]), "+f"(d[3])
        : "r"(a[0]), "r"(a[1]), "r"(a[2]), "r"(a[3]), "r"(b[0]), "r"(b[1]));
}
__device__ __forceinline__ void ldsm_x4(uint32_t* r, uint32_t addr) {
    asm volatile("ldmatrix.sync.aligned.m8n8.x4.shared.b16 {%0,%1,%2,%3}, [%4];"
                 : "=r"(r[0]), "=r"(r[1]), "=r"(r[2]), "=r"(r[3]) : "r"(addr));
}

// SMEM tile geometry: rows padded to 40 bf16 = 80B (16B aligned, conflict-free)
#define ROW_B   80
#define ARR_B   (128 * ROW_B)          // 10240 B per operand array
#define OFF_AHI 0
#define OFF_ALO (1 * ARR_B)
#define OFF_BHI (2 * ARR_B)
#define OFF_BLO (3 * ARR_B)
#define STAGE_B (4 * ARR_B)            // 40960 B per stage
#define TILE0   2048                   // meta region before tiles
#define SMEM_SZ (TILE0 + 2 * STAGE_B)  // 83968 B (2 stages)

// ---------------- kernel 0: zero counters ----------------
__global__ void zero_counts_kernel() {
    if (threadIdx.x < E_NUM) g_counts[threadIdx.x] = 0;
}

// ---------------- kernel 1: gate + top-2 routing (one warp/token) ----------------
__global__ void gate_kernel(const float* __restrict__ x,
                            const float* __restrict__ gw,
                            const float* __restrict__ gb) {
    int warp = (blockIdx.x * blockDim.x + threadIdx.x) >> 5;
    int lane = threadIdx.x & 31;
    if (warp >= N_TOK) return;
    int token = warp;

    float acc[8];
#pragma unroll
    for (int e = 0; e < 8; e++) acc[e] = 0.f;

    const float* xr = x + (size_t)token * C_DIM;
#pragma unroll 4
    for (int c = lane; c < C_DIM; c += 32) {
        float xv = xr[c];
        const float4* g4 = reinterpret_cast<const float4*>(gw + (size_t)c * E_NUM);
        float4 g0 = g4[0];
        float4 g1 = g4[1];
        acc[0] += xv * g0.x; acc[1] += xv * g0.y;
        acc[2] += xv * g0.z; acc[3] += xv * g0.w;
        acc[4] += xv * g1.x; acc[5] += xv * g1.y;
        acc[6] += xv * g1.z; acc[7] += xv * g1.w;
    }
#pragma unroll
    for (int e = 0; e < 8; e++) {
#pragma unroll
        for (int off = 16; off > 0; off >>= 1)
            acc[e] += __shfl_xor_sync(0xffffffffu, acc[e], off);
    }

    if (lane == 0) {
        float best_v = -1e30f, sec_v = -1e30f;
        int best_e = 0, sec_e = 0;
#pragma unroll
        for (int e = 0; e < 8; e++) {
            float v = acc[e] + gb[e];
            if (v > best_v) { sec_v = best_v; sec_e = best_e; best_v = v; best_e = e; }
            else if (v > sec_v) { sec_v = v; sec_e = e; }
        }
        float z  = expf(sec_v - best_v);
        float p0 = 1.0f / (1.0f + z);
        float p1 = 1.0f - p0;

        int s0 = atomicAdd(&g_counts[best_e], 1);
        g_tok [best_e * N_TOK + s0] = token;
        g_hrow[best_e * N_TOK + s0] = token * 2;
        g_prob[best_e * N_TOK + s0] = p0;

        int s1 = atomicAdd(&g_counts[sec_e], 1);
        g_tok [sec_e * N_TOK + s1] = token;
        g_hrow[sec_e * N_TOK + s1] = token * 2 + 1;
        g_prob[sec_e * N_TOK + s1] = p1;
    }
}

// ---------------- kernel 2: split x -> bf16 hi/lo ----------------
__global__ void convert_x_kernel(const float* __restrict__ x) {
    int i = blockIdx.x * blockDim.x + threadIdx.x;   // over N_TOK*C_DIM/4
    float4 v = reinterpret_cast<const float4*>(x)[i];
    float f[4] = {v.x, v.y, v.z, v.w};
    __nv_bfloat16 hi[4], lo[4];
#pragma unroll
    for (int j = 0; j < 4; j++) {
        hi[j] = __float2bfloat16_rn(f[j]);
        lo[j] = __float2bfloat16_rn(f[j] - __bfloat162float(hi[j]));
    }
    __nv_bfloat162* ph = reinterpret_cast<__nv_bfloat162*>(g_xhi);
    __nv_bfloat162* pl = reinterpret_cast<__nv_bfloat162*>(g_xlo);
    ph[i * 2 + 0] = __nv_bfloat162(hi[0], hi[1]);
    ph[i * 2 + 1] = __nv_bfloat162(hi[2], hi[3]);
    pl[i * 2 + 0] = __nv_bfloat162(lo[0], lo[1]);
    pl[i * 2 + 1] = __nv_bfloat162(lo[2], lo[3]);
}

// ---------------- kernel 3: transpose + split weights ----------------
// in: [E][R][S] fp32 -> out: [E][S][R] bf16 hi/lo. Destinations selected in
// device code (host-side __device__-symbol args bind the host shadow on GB300).
__global__ void transpose_conv_kernel(const float* __restrict__ in,
                                      int which, int R, int S) {
    __nv_bfloat16* __restrict__ ohi = which ? g_w2hi : g_w1hi;
    __nv_bfloat16* __restrict__ olo = which ? g_w2lo : g_w1lo;
    __shared__ float t[32][33];
    int e = blockIdx.z;
    int r0 = blockIdx.y * 32, s0 = blockIdx.x * 32;
    const float* ip = in + (size_t)e * R * S;
    for (int j = threadIdx.y; j < 32; j += 8)
        t[j][threadIdx.x] = ip[(size_t)(r0 + j) * S + s0 + threadIdx.x];
    __syncthreads();
    size_t ob = (size_t)e * R * S;
    for (int j = threadIdx.y; j < 32; j += 8) {
        float v = t[threadIdx.x][j];                  // in[r0+tx][s0+j]
        __nv_bfloat16 hi = __float2bfloat16_rn(v);
        __nv_bfloat16 lo = __float2bfloat16_rn(v - __bfloat162float(hi));
        size_t o = ob + (size_t)(s0 + j) * R + r0 + threadIdx.x;
        ohi[o] = hi;
        olo[o] = lo;
    }
}

// ---------------- grouped GEMM: mma.sync bf16, 3-term split ----------------
// D[128 sel rows, 128 cols] = Ahi*Bhi^T + Ahi*Blo^T + Alo*Bhi^T  (fp32 acc)
// 2-stage cp.async pipeline + ldmatrix fragment loads.
template<int KDIM, bool IS_G1>
__global__ __launch_bounds__(256, 1)
void moe_gemm_kernel(const float* __restrict__ bias) {
    constexpr int NDIM = IS_G1 ? H_DIM : C_DIM;
    constexpr int NCH  = KDIM / 32;

    int e  = blockIdx.z;
    int ne = g_counts[e];
    int m0 = blockIdx.y * 128;
    if (m0 >= ne) return;
    int n0 = blockIdx.x * 128;

    extern __shared__ char smem[];
    int*   s_hrow = (int*)(smem);            // 512 B
    float* s_prob = (float*)(smem + 512);    // 512 B
    int*   s_gidx = (int*)(smem + 1024);     // 512 B

    int tid = threadIdx.x, wid = tid >> 5, lane = tid & 31;

    if (tid < 128) {
        int idx = m0 + tid;
        int g = -1, hr = -1; float p = 0.f;
        if (idx < ne) {
            g  = IS_G1 ? g_tok[e * N_TOK + idx] : g_hrow[e * N_TOK + idx];
            hr = g_hrow[e * N_TOK + idx];
            p  = g_prob[e * N_TOK + idx];
        }
        s_gidx[tid] = g;
        s_hrow[tid] = hr;
        s_prob[tid] = p;
    }
    __syncthreads();

    const __nv_bfloat16* __restrict__ Ahi = IS_G1 ? g_xhi : g_hhi;
    const __nv_bfloat16* __restrict__ Alo = IS_G1 ? g_xlo : g_hlo;
    const __nv_bfloat16* __restrict__ Bhi = IS_G1 ? g_w1hi : g_w2hi;
    const __nv_bfloat16* __restrict__ Blo = IS_G1 ? g_w1lo : g_w2lo;

    // ---- loader mapping: thread t -> tile row t>>1, k-half t&1 (32 B) ----
    int lrow = tid >> 1, lhalf = tid & 1;
    int arow = s_gidx[lrow];
    uint32_t asz = (arow >= 0) ? 16u : 0u;   // cp.async zfill for padded rows
    size_t abase = (size_t)(arow < 0 ? 0 : arow) * KDIM + lhalf * 16;
    size_t bbase = ((size_t)e * NDIM + n0 + lrow) * KDIM + lhalf * 16;

    uint32_t tiles = (uint32_t)__cvta_generic_to_shared(smem + TILE0);
    uint32_t ldst = lrow * ROW_B + lhalf * 32;

#define LOAD_CHUNK(cc, stg)                                                     \
    do {                                                                        \
        uint32_t sbb = tiles + (stg) * STAGE_B;                                 \
        size_t ka = abase + (size_t)(cc) * 32;                                  \
        size_t kb = bbase + (size_t)(cc) * 32;                                  \
        const __nv_bfloat16* pAh = Ahi + ka;                                    \
        const __nv_bfloat16* pAl = Alo + ka;                                    \
        const __nv_bfloat16* pBh = Bhi + kb;                                    \
        const __nv_bfloat16* pBl = Blo + kb;                                    \
        cpa16(sbb + OFF_AHI + ldst,      pAh,     asz);                         \
        cpa16(sbb + OFF_AHI + ldst + 16, pAh + 8, asz);                         \
        cpa16(sbb + OFF_ALO + ldst,      pAl,     asz);                         \
        cpa16(sbb + OFF_ALO + ldst + 16, pAl + 8, asz);                         \
        cpa16(sbb + OFF_BHI + ldst,      pBh,     16u);                         \
        cpa16(sbb + OFF_BHI + ldst + 16, pBh + 8, 16u);                         \
        cpa16(sbb + OFF_BLO + ldst,      pBl,     16u);                         \
        cpa16(sbb + OFF_BLO + ldst + 16, pBl + 8, 16u);                         \
        cpa_commit();                                                           \
    } while (0)

    // prologue: chunk 0 -> stage 0
    LOAD_CHUNK(0, 0);

    // ---- compute-thread mapping ----
    int wm = wid >> 2, wn = wid & 3;     // warp tile: rows wm*64.., cols wn*32..
    int lr = lane >> 2, lc2 = (lane & 3) * 2;

    // ldmatrix per-lane source rows: quad 0: rows 0-7 k0 | 1: rows 8-15 k0
    //                                quad 2: rows 0-7 k8 | 3: rows 8-15 k8
    int qrow = lane & 7;
    int qhi  = (lane >> 3) & 1;          // +8 rows for quads 1,3
    int qk   = (lane >> 4) & 1;          // +16 B (k+8) for quads 2,3
    uint32_t aoff[4], boff[2];
#pragma unroll
    for (int mt = 0; mt < 4; mt++)
        aoff[mt] = (wm * 64 + mt * 16 + qhi * 8 + qrow) * ROW_B + qk * 16;
#pragma unroll
    for (int p = 0; p < 2; p++)
        boff[p] = (wn * 32 + p * 16 + qhi * 8 + qrow) * ROW_B + qk * 16;

    float acc[4][4][4];
#pragma unroll
    for (int mt = 0; mt < 4; mt++)
#pragma unroll
        for (int nt = 0; nt < 4; nt++)
#pragma unroll
            for (int q = 0; q < 4; q++) acc[mt][nt][q] = 0.f;

    for (int c = 0; c < NCH; c++) {
        if (c + 1 < NCH) {
            LOAD_CHUNK(c + 1, (c + 1) & 1);
            cpa_wait<1>();
        } else {
            cpa_wait<0>();
        }
        __syncthreads();   // stage c data visible to all warps

        uint32_t sb = tiles + (c & 1) * STAGE_B;
#pragma unroll
        for (int ks = 0; ks < 2; ks++) {
            uint32_t kofs = ks * 32;

            uint32_t ah[4][4];
#pragma unroll
            for (int mt = 0; mt < 4; mt++)
                ldsm_x4(ah[mt], sb + OFF_AHI + aoff[mt] + kofs);

            uint32_t bh[4][2];
#pragma unroll
            for (int p = 0; p < 2; p++) {
                uint32_t t4[4];
                ldsm_x4(t4, sb + OFF_BHI + boff[p] + kofs);
                bh[2*p + 0][0] = t4[0]; bh[2*p + 1][0] = t4[1];
                bh[2*p + 0][1] = t4[2]; bh[2*p + 1][1] = t4[3];
            }
#pragma unroll
            for (int mt = 0; mt < 4; mt++)
#pragma unroll
                for (int nt = 0; nt < 4; nt++)
                    mma_bf16(acc[mt][nt], ah[mt], bh[nt]);

            uint32_t bl[4][2];
#pragma unroll
            for (int p = 0; p < 2; p++) {
                uint32_t t4[4];
                ldsm_x4(t4, sb + OFF_BLO + boff[p] + kofs);
                bl[2*p + 0][0] = t4[0]; bl[2*p + 1][0] = t4[1];
                bl[2*p + 0][1] = t4[2]; bl[2*p + 1][1] = t4[3];
            }
#pragma unroll
            for (int mt = 0; mt < 4; mt++)
#pragma unroll
                for (int nt = 0; nt < 4; nt++)
                    mma_bf16(acc[mt][nt], ah[mt], bl[nt]);

            uint32_t al[4][4];
#pragma unroll
            for (int mt = 0; mt < 4; mt++)
                ldsm_x4(al[mt], sb + OFF_ALO + aoff[mt] + kofs);
#pragma unroll
            for (int mt = 0; mt < 4; mt++)
#pragma unroll
                for (int nt = 0; nt < 4; nt++)
                    mma_bf16(acc[mt][nt], al[mt], bh[nt]);
        }
        __syncthreads();   // all warps done reading stage c (next load reuses it)
    }

    // ---- epilogue ----
#pragma unroll
    for (int nt = 0; nt < 4; nt++) {
        int col = n0 + wn * 32 + nt * 8 + lc2;
        float bb0 = bias[(size_t)e * NDIM + col];
        float bb1 = bias[(size_t)e * NDIM + col + 1];
#pragma unroll
        for (int mt = 0; mt < 4; mt++) {
            int r0 = wm * 64 + mt * 16 + lr;
#pragma unroll
            for (int rh = 0; rh < 2; rh++) {
                int rr = r0 + rh * 8;
                int hr = s_hrow[rr];
                if (hr < 0) continue;
                float v0 = acc[mt][nt][rh * 2 + 0] + bb0;
                float v1 = acc[mt][nt][rh * 2 + 1] + bb1;
                if (IS_G1) {
                    v0 = 0.5f * v0 * (1.0f + erff(v0 * 0.70710678118654752f));
                    v1 = 0.5f * v1 * (1.0f + erff(v1 * 0.70710678118654752f));
                    __nv_bfloat16 h0 = __float2bfloat16_rn(v0);
                    __nv_bfloat16 h1 = __float2bfloat16_rn(v1);
                    __nv_bfloat16 l0 = __float2bfloat16_rn(v0 - __bfloat162float(h0));
                    __nv_bfloat16 l1 = __float2bfloat16_rn(v1 - __bfloat162float(h1));
                    size_t ob = (size_t)hr * H_DIM + col;
                    *(__nv_bfloat162*)(g_hhi + ob) = __nv_bfloat162(h0, h1);
                    *(__nv_bfloat162*)(g_hlo + ob) = __nv_bfloat162(l0, l1);
                } else {
                    float p = s_prob[rr];
                    size_t ob = (size_t)hr * C_DIM + col;
                    *(float2*)(g_outbuf + ob) = make_float2(v0 * p, v1 * p);
                }
            }
        }
    }
}

// ---------------- kernel: combine top-2 contributions ----------------
__global__ void combine_kernel(float* __restrict__ out) {
    int i = blockIdx.x * blockDim.x + threadIdx.x;
    if (i >= N_TOK * C_DIM) return;
    int t = i / C_DIM;
    int c = i - t * C_DIM;
    out[i] = g_outbuf[(size_t)(2 * t) * C_DIM + c] +
             g_outbuf[(size_t)(2 * t + 1) * C_DIM + c];
}

// ---------------- launcher ----------------
extern "C" void kernel_launch(void* const* d_in, const int* in_sizes, int n_in,
                              void* d_out, int out_size) {
    const float* x      = (const float*)d_in[0];
    const float* gate_w = (const float*)d_in[1];
    const float* gate_b = (const float*)d_in[2];
    const float* w1     = (const float*)d_in[3];
    const float* b1     = (const float*)d_in[4];
    const float* w2     = (const float*)d_in[5];
    const float* b2     = (const float*)d_in[6];
    float* out = (float*)d_out;

    cudaFuncSetAttribute(moe_gemm_kernel<C_DIM, true>,
                         cudaFuncAttributeMaxDynamicSharedMemorySize, SMEM_SZ);
    cudaFuncSetAttribute(moe_gemm_kernel<H_DIM, false>,
                         cudaFuncAttributeMaxDynamicSharedMemorySize, SMEM_SZ);

    zero_counts_kernel<<<1, 32>>>();
    gate_kernel<<<N_TOK / 8, 256>>>(x, gate_w, gate_b);
    convert_x_kernel<<<(N_TOK * C_DIM / 4) / 256, 256>>>(x);

    dim3 t1(H_DIM / 32, C_DIM / 32, E_NUM);   // (96, 24, 8)
    transpose_conv_kernel<<<t1, dim3(32, 8)>>>(w1, 0, C_DIM, H_DIM);
    dim3 t2(C_DIM / 32, H_DIM / 32, E_NUM);   // (24, 96, 8)
    transpose_conv_kernel<<<t2, dim3(32, 8)>>>(w2, 1, H_DIM, C_DIM);

    dim3 g1(H_DIM / 128, 64, E_NUM);          // (24, 64, 8)
    moe_gemm_kernel<C_DIM, true><<<g1, 256, SMEM_SZ>>>(b1);

    dim3 g2(C_DIM / 128, 64, E_NUM);          // (6, 64, 8)
    moe_gemm_kernel<H_DIM, false><<<g2, 256, SMEM_SZ>>>(b2);

    combine_kernel<<<(N_TOK * C_DIM + 255) / 256, 256>>>(out);
}

// round 8
// speedup vs baseline: 2.6825x; 1.3259x over previous
#include <cuda_runtime.h>
#include <cuda_fp16.h>
#include <math.h>
#include <stdint.h>

#define N_TOK 8192
#define C_DIM 768
#define E_NUM 8
#define H_DIM 3072
#define NSEL  (2*N_TOK)
#define KC    64

// ---------------- device scratch (no runtime allocation) ----------------
__device__ int   g_counts[E_NUM];
__device__ int   g_tok [E_NUM*N_TOK];
__device__ int   g_hrow[E_NUM*N_TOK];
__device__ float g_prob[E_NUM*N_TOK];
__device__ __half g_xh [N_TOK*C_DIM];
__device__ __half g_w1h[E_NUM*C_DIM*H_DIM];   // native [e][c][h] = [k][n]
__device__ __half g_w2h[E_NUM*H_DIM*C_DIM];   // native [e][h][c] = [k][n]
__device__ __half g_hh [(size_t)NSEL*H_DIM];
__device__ float  g_outbuf[(size_t)NSEL*C_DIM];

// ---------------- low-level helpers (sm_80-era baseline) ----------------
__device__ __forceinline__ void cpa16(uint32_t dst, const void* src, uint32_t srcsz) {
    asm volatile("cp.async.cg.shared.global [%0], [%1], 16, %2;"
                 :: "r"(dst), "l"(src), "r"(srcsz) : "memory");
}
__device__ __forceinline__ void cpa_commit() {
    asm volatile("cp.async.commit_group;" ::: "memory");
}
template<int N>
__device__ __forceinline__ void cpa_wait() {
    asm volatile("cp.async.wait_group %0;" :: "n"(N) : "memory");
}
__device__ __forceinline__ void mma_f16(float* d, const uint32_t* a, const uint32_t* b) {
    asm volatile(
        "mma.sync.aligned.m16n8k16.row.col.f32.f16.f16.f32 "
        "{%0,%1,%2,%3}, {%4,%5,%6,%7}, {%8,%9}, {%0,%1,%2,%3};"
        : "+f"(d[0]), "+f"(d[1]), "+f"(d[2]), "+f"(d[3])
        : "r"(a[0]), "r"(a[1]), "r"(a[2]), "r"(a[3]), "r"(b[0]), "r"(b[1]));
}
__device__ __forceinline__ void ldsm_x4(uint32_t* r, uint32_t addr) {
    asm volatile("ldmatrix.sync.aligned.m8n8.x4.shared.b16 {%0,%1,%2,%3}, [%4];"
                 : "=r"(r[0]), "=r"(r[1]), "=r"(r[2]), "=r"(r[3]) : "r"(addr));
}
__device__ __forceinline__ void ldsm_x4_t(uint32_t* r, uint32_t addr) {
    asm volatile("ldmatrix.sync.aligned.m8n8.x4.trans.shared.b16 {%0,%1,%2,%3}, [%4];"
                 : "=r"(r[0]), "=r"(r[1]), "=r"(r[2]), "=r"(r[3]) : "r"(addr));
}

// SMEM geometry. Pads chosen so LDSM's 8 row-addresses hit distinct 16B banks:
// A pitch 144B (144/16=9 -> r mod 8), B pitch 272B (272/16=17 -> r mod 8).
#define A_PITCH 144
#define B_PITCH 272
#define A_BYTES (128 * A_PITCH)          // 18432
#define B_BYTES (KC * B_PITCH)           // 17408
#define OFF_B   A_BYTES
#define STAGE_B (A_BYTES + B_BYTES)      // 35840
#define TILE0   2048
#define SMEM_SZ (TILE0 + 2 * STAGE_B)    // 73728

// ---------------- kernel 0: zero counters ----------------
__global__ void zero_counts_kernel() {
    if (threadIdx.x < E_NUM) g_counts[threadIdx.x] = 0;
}

// ---------------- kernel 1: gate + top-2 routing (one warp/token) ----------------
__global__ void gate_kernel(const float* __restrict__ x,
                            const float* __restrict__ gw,
                            const float* __restrict__ gb) {
    int warp = (blockIdx.x * blockDim.x + threadIdx.x) >> 5;
    int lane = threadIdx.x & 31;
    if (warp >= N_TOK) return;
    int token = warp;

    float acc[8];
#pragma unroll
    for (int e = 0; e < 8; e++) acc[e] = 0.f;

    const float* xr = x + (size_t)token * C_DIM;
#pragma unroll 4
    for (int c = lane; c < C_DIM; c += 32) {
        float xv = xr[c];
        const float4* g4 = reinterpret_cast<const float4*>(gw + (size_t)c * E_NUM);
        float4 g0 = g4[0];
        float4 g1 = g4[1];
        acc[0] += xv * g0.x; acc[1] += xv * g0.y;
        acc[2] += xv * g0.z; acc[3] += xv * g0.w;
        acc[4] += xv * g1.x; acc[5] += xv * g1.y;
        acc[6] += xv * g1.z; acc[7] += xv * g1.w;
    }
#pragma unroll
    for (int e = 0; e < 8; e++) {
#pragma unroll
        for (int off = 16; off > 0; off >>= 1)
            acc[e] += __shfl_xor_sync(0xffffffffu, acc[e], off);
    }

    if (lane == 0) {
        float best_v = -1e30f, sec_v = -1e30f;
        int best_e = 0, sec_e = 0;
#pragma unroll
        for (int e = 0; e < 8; e++) {
            float v = acc[e] + gb[e];
            if (v > best_v) { sec_v = best_v; sec_e = best_e; best_v = v; best_e = e; }
            else if (v > sec_v) { sec_v = v; sec_e = e; }
        }
        float z  = expf(sec_v - best_v);
        float p0 = 1.0f / (1.0f + z);
        float p1 = 1.0f - p0;

        int s0 = atomicAdd(&g_counts[best_e], 1);
        g_tok [best_e * N_TOK + s0] = token;
        g_hrow[best_e * N_TOK + s0] = token * 2;
        g_prob[best_e * N_TOK + s0] = p0;

        int s1 = atomicAdd(&g_counts[sec_e], 1);
        g_tok [sec_e * N_TOK + s1] = token;
        g_hrow[sec_e * N_TOK + s1] = token * 2 + 1;
        g_prob[sec_e * N_TOK + s1] = p1;
    }
}

// ---------------- kernel 2: cast x -> fp16 ----------------
__global__ void convert_x_kernel(const float* __restrict__ x) {
    int i = blockIdx.x * blockDim.x + threadIdx.x;   // over N_TOK*C_DIM/4
    float4 v = reinterpret_cast<const float4*>(x)[i];
    __half2* p = reinterpret_cast<__half2*>(g_xh);
    p[i * 2 + 0] = __floats2half2_rn(v.x, v.y);
    p[i * 2 + 1] = __floats2half2_rn(v.z, v.w);
}

// ---------------- kernel 3: cast weights -> fp16 (streaming, no transpose) ----
// destination symbol selected in DEVICE code (GB300 host-shadow pitfall).
__global__ void convert_w_kernel(const float* __restrict__ in, int which) {
    __half* o = which ? g_w2h : g_w1h;
    size_t i = (size_t)blockIdx.x * blockDim.x + threadIdx.x;  // over E*C*H/4
    float4 v = reinterpret_cast<const float4*>(in)[i];
    __half2* p = reinterpret_cast<__half2*>(o);
    p[i * 2 + 0] = __floats2half2_rn(v.x, v.y);
    p[i * 2 + 1] = __floats2half2_rn(v.z, v.w);
}

// ---------------- grouped GEMM: single-pass fp16 mma.sync ----------------
// D[128 sel rows, 128 n] = A @ B,  A row-major gathered, B = weights [k][n]
// native row-major loaded with ldmatrix.trans. 2-stage cp.async, Kc=64.
template<int KDIM, bool IS_G1>
__global__ __launch_bounds__(256, 1)
void moe_gemm_kernel(const float* __restrict__ bias) {
    constexpr int NDIM = IS_G1 ? H_DIM : C_DIM;
    constexpr int NCH  = KDIM / KC;

    int e  = blockIdx.z;
    int ne = g_counts[e];
    int m0 = blockIdx.y * 128;
    if (m0 >= ne) return;
    int n0 = blockIdx.x * 128;

    extern __shared__ char smem[];
    int*   s_hrow = (int*)(smem);            // 512 B
    float* s_prob = (float*)(smem + 512);    // 512 B
    int*   s_gidx = (int*)(smem + 1024);     // 512 B

    int tid = threadIdx.x, wid = tid >> 5, lane = tid & 31;

    if (tid < 128) {
        int idx = m0 + tid;
        int g = -1, hr = -1; float p = 0.f;
        if (idx < ne) {
            g  = IS_G1 ? g_tok[e * N_TOK + idx] : g_hrow[e * N_TOK + idx];
            hr = g_hrow[e * N_TOK + idx];
            p  = g_prob[e * N_TOK + idx];
        }
        s_gidx[tid] = g;
        s_hrow[tid] = hr;
        s_prob[tid] = p;
    }
    __syncthreads();

    const __half* __restrict__ A = IS_G1 ? g_xh  : g_hh;
    const __half* __restrict__ B = IS_G1 ? g_w1h : g_w2h;

    // ---- loaders ----
    // A: thr t -> tile row t>>1, 64B quarter t&1 (KC=64 fp16 = 128B/row)
    int arowi = tid >> 1, aq = tid & 1;
    int arow  = s_gidx[arowi];
    uint32_t asz = (arow >= 0) ? 16u : 0u;
    size_t abase = (size_t)(arow < 0 ? 0 : arow) * KDIM + aq * 32;
    uint32_t adst = arowi * A_PITCH + aq * 64;
    // B: thr t -> k-row t>>2, 64B quarter t&3 (128 n fp16 = 256B/row)
    int bk = tid >> 2, bq = tid & 3;
    size_t bbase = ((size_t)e * KDIM) * NDIM + (size_t)bk * NDIM + n0 + bq * 32;
    uint32_t bdst = OFF_B + bk * B_PITCH + bq * 64;

    uint32_t tiles = (uint32_t)__cvta_generic_to_shared(smem + TILE0);

#define LOAD_CHUNK(cc, stg)                                                  \
    do {                                                                     \
        uint32_t sbb = tiles + (stg) * STAGE_B;                              \
        const __half* pA = A + abase + (size_t)(cc) * KC;                    \
        const __half* pB = B + bbase + (size_t)(cc) * KC * NDIM;             \
        cpa16(sbb + adst,      pA,      asz);                                \
        cpa16(sbb + adst + 16, pA + 8,  asz);                                \
        cpa16(sbb + adst + 32, pA + 16, asz);                                \
        cpa16(sbb + adst + 48, pA + 24, asz);                                \
        cpa16(sbb + bdst,      pB,      16u);                                \
        cpa16(sbb + bdst + 16, pB + 8,  16u);                                \
        cpa16(sbb + bdst + 32, pB + 16, 16u);                                \
        cpa16(sbb + bdst + 48, pB + 24, 16u);                                \
        cpa_commit();                                                        \
    } while (0)

    LOAD_CHUNK(0, 0);

    // ---- compute mapping ----
    int wm = wid >> 2, wn = wid & 3;     // warp tile: rows wm*64.., cols wn*32..
    int lr = lane >> 2, lc2 = (lane & 3) * 2;

    // LDSM lane->address components
    int q8  = (lane & 7) + ((lane >> 3) & 1) * 8;   // row within 16-block
    int qk  = (lane >> 4) & 1;                       // second 16B column
    uint32_t aoff[4];
#pragma unroll
    for (int mt = 0; mt < 4; mt++)
        aoff[mt] = (uint32_t)((wm * 64 + mt * 16 + q8) * A_PITCH + qk * 16);
    uint32_t boff[2];
#pragma unroll
    for (int p = 0; p < 2; p++)
        boff[p] = (uint32_t)(OFF_B + q8 * B_PITCH + (wn * 32 + p * 16) * 2 + qk * 16);

    float acc[4][4][4];
#pragma unroll
    for (int mt = 0; mt < 4; mt++)
#pragma unroll
        for (int nt = 0; nt < 4; nt++)
#pragma unroll
            for (int q = 0; q < 4; q++) acc[mt][nt][q] = 0.f;

    for (int c = 0; c < NCH; c++) {
        if (c + 1 < NCH) {
            LOAD_CHUNK(c + 1, (c + 1) & 1);
            cpa_wait<1>();
        } else {
            cpa_wait<0>();
        }
        __syncthreads();   // stage c visible

        uint32_t sb = tiles + (c & 1) * STAGE_B;
#pragma unroll
        for (int ks = 0; ks < KC / 16; ks++) {
            uint32_t ah[4][4];
#pragma unroll
            for (int mt = 0; mt < 4; mt++)
                ldsm_x4(ah[mt], sb + aoff[mt] + ks * 32);

            uint32_t bf[4][2];
#pragma unroll
            for (int p = 0; p < 2; p++) {
                uint32_t t4[4];
                ldsm_x4_t(t4, sb + boff[p] + ks * 16 * B_PITCH);
                // quads: 0=(k0-7,n0-7) 1=(k8-15,n0-7) 2=(k0-7,n8-15) 3=(k8-15,n8-15)
                // mma b-operand: b[0]=k0-7, b[1]=k8-15 for fixed n-block
                bf[2*p + 0][0] = t4[0]; bf[2*p + 0][1] = t4[1];
                bf[2*p + 1][0] = t4[2]; bf[2*p + 1][1] = t4[3];
            }
#pragma unroll
            for (int mt = 0; mt < 4; mt++)
#pragma unroll
                for (int nt = 0; nt < 4; nt++)
                    mma_f16(acc[mt][nt], ah[mt], bf[nt]);
        }
        __syncthreads();   // all warps done reading stage c
    }

    // ---- epilogue ----
#pragma unroll
    for (int nt = 0; nt < 4; nt++) {
        int col = n0 + wn * 32 + nt * 8 + lc2;
        float bb0 = bias[(size_t)e * NDIM + col];
        float bb1 = bias[(size_t)e * NDIM + col + 1];
#pragma unroll
        for (int mt = 0; mt < 4; mt++) {
            int r0 = wm * 64 + mt * 16 + lr;
#pragma unroll
            for (int rh = 0; rh < 2; rh++) {
                int rr = r0 + rh * 8;
                int hr = s_hrow[rr];
                if (hr < 0) continue;
                float v0 = acc[mt][nt][rh * 2 + 0] + bb0;
                float v1 = acc[mt][nt][rh * 2 + 1] + bb1;
                if (IS_G1) {
                    v0 = 0.5f * v0 * (1.0f + erff(v0 * 0.70710678118654752f));
                    v1 = 0.5f * v1 * (1.0f + erff(v1 * 0.70710678118654752f));
                    *(__half2*)(g_hh + (size_t)hr * H_DIM + col) =
                        __floats2half2_rn(v0, v1);
                } else {
                    float p = s_prob[rr];
                    *(float2*)(g_outbuf + (size_t)hr * C_DIM + col) =
                        make_float2(v0 * p, v1 * p);
                }
            }
        }
    }
}

// ---------------- kernel: combine top-2 contributions ----------------
__global__ void combine_kernel(float* __restrict__ out) {
    int i = blockIdx.x * blockDim.x + threadIdx.x;
    if (i >= N_TOK * C_DIM) return;
    int t = i / C_DIM;
    int c = i - t * C_DIM;
    out[i] = g_outbuf[(size_t)(2 * t) * C_DIM + c] +
             g_outbuf[(size_t)(2 * t + 1) * C_DIM + c];
}

// ---------------- launcher ----------------
extern "C" void kernel_launch(void* const* d_in, const int* in_sizes, int n_in,
                              void* d_out, int out_size) {
    const float* x      = (const float*)d_in[0];
    const float* gate_w = (const float*)d_in[1];
    const float* gate_b = (const float*)d_in[2];
    const float* w1     = (const float*)d_in[3];
    const float* b1     = (const float*)d_in[4];
    const float* w2     = (const float*)d_in[5];
    const float* b2     = (const float*)d_in[6];
    float* out = (float*)d_out;

    cudaFuncSetAttribute(moe_gemm_kernel<C_DIM, true>,
                         cudaFuncAttributeMaxDynamicSharedMemorySize, SMEM_SZ);
    cudaFuncSetAttribute(moe_gemm_kernel<H_DIM, false>,
                         cudaFuncAttributeMaxDynamicSharedMemorySize, SMEM_SZ);

    zero_counts_kernel<<<1, 32>>>();
    gate_kernel<<<N_TOK / 8, 256>>>(x, gate_w, gate_b);
    convert_x_kernel<<<(N_TOK * C_DIM / 4) / 256, 256>>>(x);

    int wquads = E_NUM * C_DIM * H_DIM / 4;           // 4718592
    convert_w_kernel<<<wquads / 256, 256>>>(w1, 0);
    convert_w_kernel<<<wquads / 256, 256>>>(w2, 1);

    dim3 g1(H_DIM / 128, 64, E_NUM);          // (24, 64, 8)
    moe_gemm_kernel<C_DIM, true><<<g1, 256, SMEM_SZ>>>(b1);

    dim3 g2(C_DIM / 128, 64, E_NUM);          // (6, 64, 8)
    moe_gemm_kernel<H_DIM, false><<<g2, 256, SMEM_SZ>>>(b2);

    combine_kernel<<<(N_TOK * C_DIM + 255) / 256, 256>>>(out);
}

// round 9
// speedup vs baseline: 4.8525x; 1.8090x over previous
#include <cuda_runtime.h>
#include <cuda_fp16.h>
#include <math.h>
#include <stdint.h>

#define N_TOK 8192
#define C_DIM 768
#define E_NUM 8
#define H_DIM 3072
#define NSEL  (2*N_TOK)
#define KC    64
#define MT    256          // M tile (sel rows per block)

// ---------------- device scratch (no runtime allocation) ----------------
__device__ int   g_counts[E_NUM];
__device__ int   g_tok [E_NUM*N_TOK];
__device__ int   g_hrow[E_NUM*N_TOK];
__device__ float g_prob[E_NUM*N_TOK];
__device__ __half g_xh [N_TOK*C_DIM];
__device__ __half g_w1h[E_NUM*C_DIM*H_DIM];   // native [e][c][h] = [k][n]
__device__ __half g_w2h[E_NUM*H_DIM*C_DIM];   // native [e][h][c] = [k][n]
__device__ __half g_hh [(size_t)NSEL*H_DIM];
__device__ float  g_outbuf[(size_t)NSEL*C_DIM];

// ---------------- low-level helpers (sm_80-era baseline) ----------------
__device__ __forceinline__ void cpa16(uint32_t dst, const void* src, uint32_t srcsz) {
    asm volatile("cp.async.cg.shared.global [%0], [%1], 16, %2;"
                 :: "r"(dst), "l"(src), "r"(srcsz) : "memory");
}
__device__ __forceinline__ void cpa_commit() {
    asm volatile("cp.async.commit_group;" ::: "memory");
}
template<int N>
__device__ __forceinline__ void cpa_wait() {
    asm volatile("cp.async.wait_group %0;" :: "n"(N) : "memory");
}
__device__ __forceinline__ void mma_f16(float* d, const uint32_t* a, const uint32_t* b) {
    asm volatile(
        "mma.sync.aligned.m16n8k16.row.col.f32.f16.f16.f32 "
        "{%0,%1,%2,%3}, {%4,%5,%6,%7}, {%8,%9}, {%0,%1,%2,%3};"
        : "+f"(d[0]), "+f"(d[1]), "+f"(d[2]), "+f"(d[3])
        : "r"(a[0]), "r"(a[1]), "r"(a[2]), "r"(a[3]), "r"(b[0]), "r"(b[1]));
}
__device__ __forceinline__ void ldsm_x4(uint32_t* r, uint32_t addr) {
    asm volatile("ldmatrix.sync.aligned.m8n8.x4.shared.b16 {%0,%1,%2,%3}, [%4];"
                 : "=r"(r[0]), "=r"(r[1]), "=r"(r[2]), "=r"(r[3]) : "r"(addr));
}
__device__ __forceinline__ void ldsm_x4_t(uint32_t* r, uint32_t addr) {
    asm volatile("ldmatrix.sync.aligned.m8n8.x4.trans.shared.b16 {%0,%1,%2,%3}, [%4];"
                 : "=r"(r[0]), "=r"(r[1]), "=r"(r[2]), "=r"(r[3]) : "r"(addr));
}

// SMEM geometry. Pads chosen so LDSM's 8 row-addresses hit distinct 16B banks:
// A pitch 144B (144/16=9 -> r mod 8), B pitch 272B (272/16=17 -> r mod 8).
#define A_PITCH 144
#define B_PITCH 272
#define A_BYTES (MT * A_PITCH)           // 36864
#define B_BYTES (KC * B_PITCH)           // 17408
#define OFF_B   A_BYTES
#define STAGE_B (A_BYTES + B_BYTES)      // 54272
#define TILE0   4096
#define SMEM_SZ (TILE0 + 2 * STAGE_B)    // 112640

// ---------------- kernel 0: zero counters ----------------
__global__ void zero_counts_kernel() {
    if (threadIdx.x < E_NUM) g_counts[threadIdx.x] = 0;
}

// ---------------- kernel 1: gate + top-2 routing (one warp/token) ----------------
__global__ void gate_kernel(const float* __restrict__ x,
                            const float* __restrict__ gw,
                            const float* __restrict__ gb) {
    int warp = (blockIdx.x * blockDim.x + threadIdx.x) >> 5;
    int lane = threadIdx.x & 31;
    if (warp >= N_TOK) return;
    int token = warp;

    float acc[8];
#pragma unroll
    for (int e = 0; e < 8; e++) acc[e] = 0.f;

    const float* xr = x + (size_t)token * C_DIM;
#pragma unroll 4
    for (int c = lane; c < C_DIM; c += 32) {
        float xv = xr[c];
        const float4* g4 = reinterpret_cast<const float4*>(gw + (size_t)c * E_NUM);
        float4 g0 = g4[0];
        float4 g1 = g4[1];
        acc[0] += xv * g0.x; acc[1] += xv * g0.y;
        acc[2] += xv * g0.z; acc[3] += xv * g0.w;
        acc[4] += xv * g1.x; acc[5] += xv * g1.y;
        acc[6] += xv * g1.z; acc[7] += xv * g1.w;
    }
#pragma unroll
    for (int e = 0; e < 8; e++) {
#pragma unroll
        for (int off = 16; off > 0; off >>= 1)
            acc[e] += __shfl_xor_sync(0xffffffffu, acc[e], off);
    }

    if (lane == 0) {
        float best_v = -1e30f, sec_v = -1e30f;
        int best_e = 0, sec_e = 0;
#pragma unroll
        for (int e = 0; e < 8; e++) {
            float v = acc[e] + gb[e];
            if (v > best_v) { sec_v = best_v; sec_e = best_e; best_v = v; best_e = e; }
            else if (v > sec_v) { sec_v = v; sec_e = e; }
        }
        float z  = expf(sec_v - best_v);
        float p0 = 1.0f / (1.0f + z);
        float p1 = 1.0f - p0;

        int s0 = atomicAdd(&g_counts[best_e], 1);
        g_tok [best_e * N_TOK + s0] = token;
        g_hrow[best_e * N_TOK + s0] = token * 2;
        g_prob[best_e * N_TOK + s0] = p0;

        int s1 = atomicAdd(&g_counts[sec_e], 1);
        g_tok [sec_e * N_TOK + s1] = token;
        g_hrow[sec_e * N_TOK + s1] = token * 2 + 1;
        g_prob[sec_e * N_TOK + s1] = p1;
    }
}

// ---------------- kernel 2: cast x -> fp16 ----------------
__global__ void convert_x_kernel(const float* __restrict__ x) {
    int i = blockIdx.x * blockDim.x + threadIdx.x;   // over N_TOK*C_DIM/4
    float4 v = reinterpret_cast<const float4*>(x)[i];
    __half2* p = reinterpret_cast<__half2*>(g_xh);
    p[i * 2 + 0] = __floats2half2_rn(v.x, v.y);
    p[i * 2 + 1] = __floats2half2_rn(v.z, v.w);
}

// ---------------- kernel 3: cast weights -> fp16 (streaming, no transpose) ----
// destination symbol selected in DEVICE code (GB300 host-shadow pitfall).
__global__ void convert_w_kernel(const float* __restrict__ in, int which) {
    __half* o = which ? g_w2h : g_w1h;
    size_t i = (size_t)blockIdx.x * blockDim.x + threadIdx.x;  // over E*C*H/4
    float4 v = reinterpret_cast<const float4*>(in)[i];
    __half2* p = reinterpret_cast<__half2*>(o);
    p[i * 2 + 0] = __floats2half2_rn(v.x, v.y);
    p[i * 2 + 1] = __floats2half2_rn(v.z, v.w);
}

// ---------------- grouped GEMM: single-pass fp16 mma.sync ----------------
// D[256 sel rows, 128 n] = A @ B. 512 threads, 16 warps (4/SMSP), warp 64x32.
// A row-major gathered; B = weights [k][n] via ldmatrix.trans. 2-stage cp.async.
template<int KDIM, bool IS_G1>
__global__ __launch_bounds__(512, 1)
void moe_gemm_kernel(const float* __restrict__ bias) {
    constexpr int NDIM = IS_G1 ? H_DIM : C_DIM;
    constexpr int NCH  = KDIM / KC;

    int e  = blockIdx.z;
    int ne = g_counts[e];
    int m0 = blockIdx.y * MT;
    if (m0 >= ne) return;
    int n0 = blockIdx.x * 128;

    extern __shared__ char smem[];
    int*   s_hrow = (int*)(smem);             // 1024 B
    float* s_prob = (float*)(smem + 1024);    // 1024 B
    int*   s_gidx = (int*)(smem + 2048);      // 1024 B

    int tid = threadIdx.x, wid = tid >> 5, lane = tid & 31;

    if (tid < MT) {
        int idx = m0 + tid;
        int g = -1, hr = -1; float p = 0.f;
        if (idx < ne) {
            g  = IS_G1 ? g_tok[e * N_TOK + idx] : g_hrow[e * N_TOK + idx];
            hr = g_hrow[e * N_TOK + idx];
            p  = g_prob[e * N_TOK + idx];
        }
        s_gidx[tid] = g;
        s_hrow[tid] = hr;
        s_prob[tid] = p;
    }
    __syncthreads();

    const __half* __restrict__ A = IS_G1 ? g_xh  : g_hh;
    const __half* __restrict__ B = IS_G1 ? g_w1h : g_w2h;

    // ---- loaders ----
    // A: thr t -> tile row t>>1 (0..255), 64B half t&1 (KC=64 fp16 = 128B/row)
    int arowi = tid >> 1, aq = tid & 1;
    int arow  = s_gidx[arowi];
    uint32_t asz = (arow >= 0) ? 16u : 0u;
    size_t abase = (size_t)(arow < 0 ? 0 : arow) * KDIM + aq * 32;
    uint32_t adst = arowi * A_PITCH + aq * 64;
    // B: thr t -> k-row t>>3 (0..63), 32B eighth t&7 (128 n fp16 = 256B/row)
    int bk = tid >> 3, bq = tid & 7;
    size_t bbase = ((size_t)e * KDIM) * NDIM + (size_t)bk * NDIM + n0 + bq * 16;
    uint32_t bdst = OFF_B + bk * B_PITCH + bq * 32;

    uint32_t tiles = (uint32_t)__cvta_generic_to_shared(smem + TILE0);

#define LOAD_CHUNK(cc, stg)                                                  \
    do {                                                                     \
        uint32_t sbb = tiles + (stg) * STAGE_B;                              \
        const __half* pA = A + abase + (size_t)(cc) * KC;                    \
        const __half* pB = B + bbase + (size_t)(cc) * KC * NDIM;             \
        cpa16(sbb + adst,      pA,      asz);                                \
        cpa16(sbb + adst + 16, pA + 8,  asz);                                \
        cpa16(sbb + adst + 32, pA + 16, asz);                                \
        cpa16(sbb + adst + 48, pA + 24, asz);                                \
        cpa16(sbb + bdst,      pB,      16u);                                \
        cpa16(sbb + bdst + 16, pB + 8,  16u);                                \
        cpa_commit();                                                        \
    } while (0)

    LOAD_CHUNK(0, 0);

    // ---- compute mapping: 16 warps, wm = wid>>2 (rows wm*64), wn = wid&3 ----
    int wm = wid >> 2, wn = wid & 3;
    int lr = lane >> 2, lc2 = (lane & 3) * 2;

    // LDSM lane->address components
    int q8  = (lane & 7) + ((lane >> 3) & 1) * 8;   // row within 16-block
    int qk  = (lane >> 4) & 1;                       // second 16B column
    uint32_t aoff[4];
#pragma unroll
    for (int mt = 0; mt < 4; mt++)
        aoff[mt] = (uint32_t)((wm * 64 + mt * 16 + q8) * A_PITCH + qk * 16);
    uint32_t boff[2];
#pragma unroll
    for (int p = 0; p < 2; p++)
        boff[p] = (uint32_t)(OFF_B + q8 * B_PITCH + (wn * 32 + p * 16) * 2 + qk * 16);

    float acc[4][4][4];
#pragma unroll
    for (int mt = 0; mt < 4; mt++)
#pragma unroll
        for (int nt = 0; nt < 4; nt++)
#pragma unroll
            for (int q = 0; q < 4; q++) acc[mt][nt][q] = 0.f;

    for (int c = 0; c < NCH; c++) {
        if (c + 1 < NCH) {
            LOAD_CHUNK(c + 1, (c + 1) & 1);
            cpa_wait<1>();
        } else {
            cpa_wait<0>();
        }
        __syncthreads();   // stage c visible

        uint32_t sb = tiles + (c & 1) * STAGE_B;
#pragma unroll
        for (int ks = 0; ks < KC / 16; ks++) {
            uint32_t ah[4][4];
#pragma unroll
            for (int mt = 0; mt < 4; mt++)
                ldsm_x4(ah[mt], sb + aoff[mt] + ks * 32);

            uint32_t bf[4][2];
#pragma unroll
            for (int p = 0; p < 2; p++) {
                uint32_t t4[4];
                ldsm_x4_t(t4, sb + boff[p] + ks * 16 * B_PITCH);
                // quads: 0=(k0-7,n0-7) 1=(k8-15,n0-7) 2=(k0-7,n8-15) 3=(k8-15,n8-15)
                bf[2*p + 0][0] = t4[0]; bf[2*p + 0][1] = t4[1];
                bf[2*p + 1][0] = t4[2]; bf[2*p + 1][1] = t4[3];
            }
#pragma unroll
            for (int mt = 0; mt < 4; mt++)
#pragma unroll
                for (int nt = 0; nt < 4; nt++)
                    mma_f16(acc[mt][nt], ah[mt], bf[nt]);
        }
        __syncthreads();   // all warps done reading stage c
    }

    // ---- epilogue ----
#pragma unroll
    for (int nt = 0; nt < 4; nt++) {
        int col = n0 + wn * 32 + nt * 8 + lc2;
        float bb0 = bias[(size_t)e * NDIM + col];
        float bb1 = bias[(size_t)e * NDIM + col + 1];
#pragma unroll
        for (int mt = 0; mt < 4; mt++) {
            int r0 = wm * 64 + mt * 16 + lr;
#pragma unroll
            for (int rh = 0; rh < 2; rh++) {
                int rr = r0 + rh * 8;
                int hr = s_hrow[rr];
                if (hr < 0) continue;
                float v0 = acc[mt][nt][rh * 2 + 0] + bb0;
                float v1 = acc[mt][nt][rh * 2 + 1] + bb1;
                if (IS_G1) {
                    v0 = 0.5f * v0 * (1.0f + erff(v0 * 0.70710678118654752f));
                    v1 = 0.5f * v1 * (1.0f + erff(v1 * 0.70710678118654752f));
                    *(__half2*)(g_hh + (size_t)hr * H_DIM + col) =
                        __floats2half2_rn(v0, v1);
                } else {
                    float p = s_prob[rr];
                    *(float2*)(g_outbuf + (size_t)hr * C_DIM + col) =
                        make_float2(v0 * p, v1 * p);
                }
            }
        }
    }
}

// ---------------- kernel: combine top-2 contributions ----------------
__global__ void combine_kernel(float* __restrict__ out) {
    int i = blockIdx.x * blockDim.x + threadIdx.x;
    if (i >= N_TOK * C_DIM) return;
    int t = i / C_DIM;
    int c = i - t * C_DIM;
    out[i] = g_outbuf[(size_t)(2 * t) * C_DIM + c] +
             g_outbuf[(size_t)(2 * t + 1) * C_DIM + c];
}

// ---------------- launcher ----------------
extern "C" void kernel_launch(void* const* d_in, const int* in_sizes, int n_in,
                              void* d_out, int out_size) {
    const float* x      = (const float*)d_in[0];
    const float* gate_w = (const float*)d_in[1];
    const float* gate_b = (const float*)d_in[2];
    const float* w1     = (const float*)d_in[3];
    const float* b1     = (const float*)d_in[4];
    const float* w2     = (const float*)d_in[5];
    const float* b2     = (const float*)d_in[6];
    float* out = (float*)d_out;

    cudaFuncSetAttribute(moe_gemm_kernel<C_DIM, true>,
                         cudaFuncAttributeMaxDynamicSharedMemorySize, SMEM_SZ);
    cudaFuncSetAttribute(moe_gemm_kernel<H_DIM, false>,
                         cudaFuncAttributeMaxDynamicSharedMemorySize, SMEM_SZ);

    zero_counts_kernel<<<1, 32>>>();
    gate_kernel<<<N_TOK / 8, 256>>>(x, gate_w, gate_b);
    convert_x_kernel<<<(N_TOK * C_DIM / 4) / 256, 256>>>(x);

    int wquads = E_NUM * C_DIM * H_DIM / 4;           // 4718592
    convert_w_kernel<<<wquads / 256, 256>>>(w1, 0);
    convert_w_kernel<<<wquads / 256, 256>>>(w2, 1);

    dim3 g1(H_DIM / 128, N_TOK / MT, E_NUM);   // (24, 32, 8)
    moe_gemm_kernel<C_DIM, true><<<g1, 512, SMEM_SZ>>>(b1);

    dim3 g2(C_DIM / 128, N_TOK / MT, E_NUM);   // (6, 32, 8)
    moe_gemm_kernel<H_DIM, false><<<g2, 512, SMEM_SZ>>>(b2);

    combine_kernel<<<(N_TOK * C_DIM + 255) / 256, 256>>>(out);
}

// round 10
// speedup vs baseline: 5.0888x; 1.0487x over previous
#include <cuda_runtime.h>
#include <cuda_fp16.h>
#include <math.h>
#include <stdint.h>

#define N_TOK 8192
#define C_DIM 768
#define E_NUM 8
#define H_DIM 3072
#define NSEL  (2*N_TOK)
#define KC    64
#define MT    256          // M tile (sel rows per block)

// ---------------- device scratch (no runtime allocation) ----------------
__device__ int   g_counts[E_NUM];
__device__ int   g_tok [E_NUM*N_TOK];
__device__ int   g_hrow[E_NUM*N_TOK];
__device__ float g_prob[E_NUM*N_TOK];
__device__ __half g_xh [N_TOK*C_DIM];
__device__ __half g_w1h[E_NUM*C_DIM*H_DIM];   // native [e][c][h] = [k][n]
__device__ __half g_w2h[E_NUM*H_DIM*C_DIM];   // native [e][h][c] = [k][n]
__device__ __half g_hh [(size_t)NSEL*H_DIM];
__device__ float  g_outbuf[(size_t)NSEL*C_DIM];

// ---------------- low-level helpers (sm_80-era baseline) ----------------
__device__ __forceinline__ void cpa16(uint32_t dst, const void* src, uint32_t srcsz) {
    asm volatile("cp.async.cg.shared.global [%0], [%1], 16, %2;"
                 :: "r"(dst), "l"(src), "r"(srcsz) : "memory");
}
__device__ __forceinline__ void cpa_commit() {
    asm volatile("cp.async.commit_group;" ::: "memory");
}
template<int N>
__device__ __forceinline__ void cpa_wait() {
    asm volatile("cp.async.wait_group %0;" :: "n"(N) : "memory");
}
__device__ __forceinline__ void mma_f16(float* d, const uint32_t* a, const uint32_t* b) {
    asm volatile(
        "mma.sync.aligned.m16n8k16.row.col.f32.f16.f16.f32 "
        "{%0,%1,%2,%3}, {%4,%5,%6,%7}, {%8,%9}, {%0,%1,%2,%3};"
        : "+f"(d[0]), "+f"(d[1]), "+f"(d[2]), "+f"(d[3])
        : "r"(a[0]), "r"(a[1]), "r"(a[2]), "r"(a[3]), "r"(b[0]), "r"(b[1]));
}
__device__ __forceinline__ void ldsm_x4(uint32_t* r, uint32_t addr) {
    asm volatile("ldmatrix.sync.aligned.m8n8.x4.shared.b16 {%0,%1,%2,%3}, [%4];"
                 : "=r"(r[0]), "=r"(r[1]), "=r"(r[2]), "=r"(r[3]) : "r"(addr));
}
__device__ __forceinline__ void ldsm_x4_t(uint32_t* r, uint32_t addr) {
    asm volatile("ldmatrix.sync.aligned.m8n8.x4.trans.shared.b16 {%0,%1,%2,%3}, [%4];"
                 : "=r"(r[0]), "=r"(r[1]), "=r"(r[2]), "=r"(r[3]) : "r"(addr));
}

// SMEM geometry (LDSM conflict-free pitches: 144/16=9, 272/16=17 -> r mod 8)
#define A_PITCH 144
#define B_PITCH 272
#define A_BYTES (MT * A_PITCH)           // 36864
#define B_BYTES (KC * B_PITCH)           // 17408
#define OFF_B   A_BYTES
#define STAGE_B (A_BYTES + B_BYTES)      // 54272
#define NSTAGE  3
#define TILE0   4096
#define SMEM_SZ (TILE0 + NSTAGE * STAGE_B)   // 166912

// prep kernel block ranges
#define WQUADS (E_NUM * C_DIM * H_DIM / 4)   // 4718592
#define WBLK   (WQUADS / 256)                // 18432
#define GATEBLK (N_TOK / 8)                  // 1024
#define XQUADS (N_TOK * C_DIM / 4)           // 1572864
#define XBLK   (XQUADS / 256)                // 6144
#define PREP_BLOCKS (2 * WBLK + GATEBLK + XBLK)  // 44032

// ---------------- kernel 0: zero counters ----------------
__global__ void zero_counts_kernel() {
    if (threadIdx.x < E_NUM) g_counts[threadIdx.x] = 0;
}

// ---------------- fused prep: convert w1 | convert w2 | gate | convert x ----
__global__ void prep_kernel(const float* __restrict__ x,
                            const float* __restrict__ gw,
                            const float* __restrict__ gb,
                            const float* __restrict__ w1,
                            const float* __restrict__ w2) {
    int b = blockIdx.x;
    int tid = threadIdx.x;

    if (b < 2 * WBLK) {
        // ---- weight convert (destination symbol chosen in device code) ----
        const float* in = (b < WBLK) ? w1 : w2;
        __half* o = (b < WBLK) ? g_w1h : g_w2h;
        size_t i = (size_t)(b < WBLK ? b : b - WBLK) * 256 + tid;
        float4 v = reinterpret_cast<const float4*>(in)[i];
        __half2* p = reinterpret_cast<__half2*>(o);
        p[i * 2 + 0] = __floats2half2_rn(v.x, v.y);
        p[i * 2 + 1] = __floats2half2_rn(v.z, v.w);
        return;
    }
    b -= 2 * WBLK;

    if (b < GATEBLK) {
        // ---- gate + top-2 routing (one warp/token) ----
        int warp = b * 8 + (tid >> 5);
        int lane = tid & 31;
        int token = warp;

        float acc[8];
#pragma unroll
        for (int e = 0; e < 8; e++) acc[e] = 0.f;

        const float* xr = x + (size_t)token * C_DIM;
#pragma unroll 4
        for (int c = lane; c < C_DIM; c += 32) {
            float xv = xr[c];
            const float4* g4 = reinterpret_cast<const float4*>(gw + (size_t)c * E_NUM);
            float4 g0 = g4[0];
            float4 g1 = g4[1];
            acc[0] += xv * g0.x; acc[1] += xv * g0.y;
            acc[2] += xv * g0.z; acc[3] += xv * g0.w;
            acc[4] += xv * g1.x; acc[5] += xv * g1.y;
            acc[6] += xv * g1.z; acc[7] += xv * g1.w;
        }
#pragma unroll
        for (int e = 0; e < 8; e++) {
#pragma unroll
            for (int off = 16; off > 0; off >>= 1)
                acc[e] += __shfl_xor_sync(0xffffffffu, acc[e], off);
        }

        if (lane == 0) {
            float best_v = -1e30f, sec_v = -1e30f;
            int best_e = 0, sec_e = 0;
#pragma unroll
            for (int e = 0; e < 8; e++) {
                float v = acc[e] + gb[e];
                if (v > best_v) { sec_v = best_v; sec_e = best_e; best_v = v; best_e = e; }
                else if (v > sec_v) { sec_v = v; sec_e = e; }
            }
            float z  = expf(sec_v - best_v);
            float p0 = 1.0f / (1.0f + z);
            float p1 = 1.0f - p0;

            int s0 = atomicAdd(&g_counts[best_e], 1);
            g_tok [best_e * N_TOK + s0] = token;
            g_hrow[best_e * N_TOK + s0] = token * 2;
            g_prob[best_e * N_TOK + s0] = p0;

            int s1 = atomicAdd(&g_counts[sec_e], 1);
            g_tok [sec_e * N_TOK + s1] = token;
            g_hrow[sec_e * N_TOK + s1] = token * 2 + 1;
            g_prob[sec_e * N_TOK + s1] = p1;
        }
        return;
    }
    b -= GATEBLK;

    // ---- cast x -> fp16 ----
    int i = b * 256 + tid;
    float4 v = reinterpret_cast<const float4*>(x)[i];
    __half2* p = reinterpret_cast<__half2*>(g_xh);
    p[i * 2 + 0] = __floats2half2_rn(v.x, v.y);
    p[i * 2 + 1] = __floats2half2_rn(v.z, v.w);
}

// ---------------- grouped GEMM: single-pass fp16 mma.sync ----------------
// D[256 sel rows, 128 n] = A @ B. 512 threads, 16 warps, warp 64x32.
// 3-stage cp.async pipeline, ONE __syncthreads per chunk.
template<int KDIM, bool IS_G1>
__global__ __launch_bounds__(512, 1)
void moe_gemm_kernel(const float* __restrict__ bias) {
    constexpr int NDIM = IS_G1 ? H_DIM : C_DIM;
    constexpr int NCH  = KDIM / KC;

    int e  = blockIdx.z;
    int ne = g_counts[e];
    int m0 = blockIdx.y * MT;
    if (m0 >= ne) return;
    int n0 = blockIdx.x * 128;

    extern __shared__ char smem[];
    int*   s_hrow = (int*)(smem);             // 1024 B
    float* s_prob = (float*)(smem + 1024);    // 1024 B
    int*   s_gidx = (int*)(smem + 2048);      // 1024 B

    int tid = threadIdx.x, wid = tid >> 5, lane = tid & 31;

    if (tid < MT) {
        int idx = m0 + tid;
        int g = -1, hr = -1; float p = 0.f;
        if (idx < ne) {
            g  = IS_G1 ? g_tok[e * N_TOK + idx] : g_hrow[e * N_TOK + idx];
            hr = g_hrow[e * N_TOK + idx];
            p  = g_prob[e * N_TOK + idx];
        }
        s_gidx[tid] = g;
        s_hrow[tid] = hr;
        s_prob[tid] = p;
    }
    __syncthreads();

    const __half* __restrict__ A = IS_G1 ? g_xh  : g_hh;
    const __half* __restrict__ B = IS_G1 ? g_w1h : g_w2h;

    // ---- loaders ----
    int arowi = tid >> 1, aq = tid & 1;
    int arow  = s_gidx[arowi];
    uint32_t asz = (arow >= 0) ? 16u : 0u;
    size_t abase = (size_t)(arow < 0 ? 0 : arow) * KDIM + aq * 32;
    uint32_t adst = arowi * A_PITCH + aq * 64;
    int bk = tid >> 3, bq = tid & 7;
    size_t bbase = ((size_t)e * KDIM) * NDIM + (size_t)bk * NDIM + n0 + bq * 16;
    uint32_t bdst = OFF_B + bk * B_PITCH + bq * 32;

    uint32_t tiles = (uint32_t)__cvta_generic_to_shared(smem + TILE0);

#define LOAD_CHUNK(cc, stg)                                                  \
    do {                                                                     \
        uint32_t sbb = tiles + (stg) * STAGE_B;                              \
        const __half* pA = A + abase + (size_t)(cc) * KC;                    \
        const __half* pB = B + bbase + (size_t)(cc) * KC * NDIM;             \
        cpa16(sbb + adst,      pA,      asz);                                \
        cpa16(sbb + adst + 16, pA + 8,  asz);                                \
        cpa16(sbb + adst + 32, pA + 16, asz);                                \
        cpa16(sbb + adst + 48, pA + 24, asz);                                \
        cpa16(sbb + bdst,      pB,      16u);                                \
        cpa16(sbb + bdst + 16, pB + 8,  16u);                                \
        cpa_commit();                                                        \
    } while (0)

    LOAD_CHUNK(0, 0);
    LOAD_CHUNK(1, 1);

    // ---- compute mapping: 16 warps, wm = wid>>2 (rows wm*64), wn = wid&3 ----
    int wm = wid >> 2, wn = wid & 3;
    int lr = lane >> 2, lc2 = (lane & 3) * 2;

    int q8  = (lane & 7) + ((lane >> 3) & 1) * 8;   // LDSM row within 16-block
    int qk  = (lane >> 4) & 1;                       // second 16B column
    uint32_t aoff[4];
#pragma unroll
    for (int mt = 0; mt < 4; mt++)
        aoff[mt] = (uint32_t)((wm * 64 + mt * 16 + q8) * A_PITCH + qk * 16);
    uint32_t boff[2];
#pragma unroll
    for (int p = 0; p < 2; p++)
        boff[p] = (uint32_t)(OFF_B + q8 * B_PITCH + (wn * 32 + p * 16) * 2 + qk * 16);

    float acc[4][4][4];
#pragma unroll
    for (int mt = 0; mt < 4; mt++)
#pragma unroll
        for (int nt = 0; nt < 4; nt++)
#pragma unroll
            for (int q = 0; q < 4; q++) acc[mt][nt][q] = 0.f;

    int s_cur = 0, s_ld = 2;   // compute stage / stage for chunk c+2
    for (int c = 0; c < NCH; c++) {
        // chunk c arrived? (pending groups after commits 0..c+1: exactly 1)
        if (c + 1 < NCH) { cpa_wait<1>(); } else { cpa_wait<0>(); }
        __syncthreads();   // all warps done reading stage s_ld's previous tenant
        if (c + 2 < NCH) LOAD_CHUNK(c + 2, s_ld);

        uint32_t sb = tiles + s_cur * STAGE_B;
#pragma unroll
        for (int ks = 0; ks < KC / 16; ks++) {
            uint32_t ah[4][4];
#pragma unroll
            for (int mt = 0; mt < 4; mt++)
                ldsm_x4(ah[mt], sb + aoff[mt] + ks * 32);

            uint32_t bf[4][2];
#pragma unroll
            for (int p = 0; p < 2; p++) {
                uint32_t t4[4];
                ldsm_x4_t(t4, sb + boff[p] + ks * 16 * B_PITCH);
                // quads: 0=(k0-7,n0-7) 1=(k8-15,n0-7) 2=(k0-7,n8-15) 3=(k8-15,n8-15)
                bf[2*p + 0][0] = t4[0]; bf[2*p + 0][1] = t4[1];
                bf[2*p + 1][0] = t4[2]; bf[2*p + 1][1] = t4[3];
            }
#pragma unroll
            for (int mt = 0; mt < 4; mt++)
#pragma unroll
                for (int nt = 0; nt < 4; nt++)
                    mma_f16(acc[mt][nt], ah[mt], bf[nt]);
        }
        s_cur = (s_cur == 2) ? 0 : s_cur + 1;
        s_ld  = (s_ld  == 2) ? 0 : s_ld  + 1;
    }

    // ---- epilogue ----
#pragma unroll
    for (int nt = 0; nt < 4; nt++) {
        int col = n0 + wn * 32 + nt * 8 + lc2;
        float bb0 = bias[(size_t)e * NDIM + col];
        float bb1 = bias[(size_t)e * NDIM + col + 1];
#pragma unroll
        for (int mt = 0; mt < 4; mt++) {
            int r0 = wm * 64 + mt * 16 + lr;
#pragma unroll
            for (int rh = 0; rh < 2; rh++) {
                int rr = r0 + rh * 8;
                int hr = s_hrow[rr];
                if (hr < 0) continue;
                float v0 = acc[mt][nt][rh * 2 + 0] + bb0;
                float v1 = acc[mt][nt][rh * 2 + 1] + bb1;
                if (IS_G1) {
                    v0 = 0.5f * v0 * (1.0f + erff(v0 * 0.70710678118654752f));
                    v1 = 0.5f * v1 * (1.0f + erff(v1 * 0.70710678118654752f));
                    *(__half2*)(g_hh + (size_t)hr * H_DIM + col) =
                        __floats2half2_rn(v0, v1);
                } else {
                    float p = s_prob[rr];
                    *(float2*)(g_outbuf + (size_t)hr * C_DIM + col) =
                        make_float2(v0 * p, v1 * p);
                }
            }
        }
    }
}

// ---------------- kernel: combine top-2 contributions (float4) ----------------
__global__ void combine_kernel(float* __restrict__ out) {
    int i = blockIdx.x * blockDim.x + threadIdx.x;   // over N_TOK*C_DIM/4
    int t  = i / (C_DIM / 4);
    int c4 = i - t * (C_DIM / 4);
    float4 a = *((const float4*)(g_outbuf + (size_t)(2 * t)     * C_DIM) + c4);
    float4 b = *((const float4*)(g_outbuf + (size_t)(2 * t + 1) * C_DIM) + c4);
    reinterpret_cast<float4*>(out)[i] =
        make_float4(a.x + b.x, a.y + b.y, a.z + b.z, a.w + b.w);
}

// ---------------- launcher ----------------
extern "C" void kernel_launch(void* const* d_in, const int* in_sizes, int n_in,
                              void* d_out, int out_size) {
    const float* x      = (const float*)d_in[0];
    const float* gate_w = (const float*)d_in[1];
    const float* gate_b = (const float*)d_in[2];
    const float* w1     = (const float*)d_in[3];
    const float* b1     = (const float*)d_in[4];
    const float* w2     = (const float*)d_in[5];
    const float* b2     = (const float*)d_in[6];
    float* out = (float*)d_out;

    cudaFuncSetAttribute(moe_gemm_kernel<C_DIM, true>,
                         cudaFuncAttributeMaxDynamicSharedMemorySize, SMEM_SZ);
    cudaFuncSetAttribute(moe_gemm_kernel<H_DIM, false>,
                         cudaFuncAttributeMaxDynamicSharedMemorySize, SMEM_SZ);

    zero_counts_kernel<<<1, 32>>>();
    prep_kernel<<<PREP_BLOCKS, 256>>>(x, gate_w, gate_b, w1, w2);

    dim3 g1(H_DIM / 128, N_TOK / MT, E_NUM);   // (24, 32, 8)
    moe_gemm_kernel<C_DIM, true><<<g1, 512, SMEM_SZ>>>(b1);

    dim3 g2(C_DIM / 128, N_TOK / MT, E_NUM);   // (6, 32, 8)
    moe_gemm_kernel<H_DIM, false><<<g2, 512, SMEM_SZ>>>(b2);

    combine_kernel<<<(N_TOK * C_DIM / 4) / 256, 256>>>(out);
}